// round 2
// baseline (speedup 1.0000x reference)
#include <cuda_runtime.h>

#define NB 256
#define NA 1024
#define NE 8192
#define F1 64
#define FP 128
#define SLOPE 0.01f

// ---------- device scratch (allocation-free: static globals) ----------
__device__ float g_dinv[NA];
__device__ float g_nself[NA];
__device__ int   g_rowptr[NA + 1];
__device__ int   g_csrsrc[NE];
__device__ float g_csrnorm[NE];
// h1: feature-major [b][k][i]  (coalesced write in K1, coalesced read in K2)
__device__ float g_h1[(size_t)NB * F1 * NA];
// t = h1 @ W2: row-major [b][i][j] (contiguous 256B rows for the K3 gather)
__device__ float g_t[(size_t)NB * NA * F1];

__device__ __forceinline__ float leaky(float v) {
    return v >= 0.0f ? v : SLOPE * v;
}

// ---------- K0: degrees, norms, CSR build (one block) ----------
__global__ void k_setup(const unsigned int* __restrict__ ei_raw) {
    __shared__ int   scnt[NA];
    __shared__ float sdinv[NA];
    __shared__ int   scur[NA];
    __shared__ int   s_is64;
    int tid = threadIdx.x;

    if (tid == 0) {
        // int64 edge_index has zero high words (values < 1024); int32 does not.
        int any = 0;
        for (int w = 1; w < 64; w += 2) any |= (ei_raw[w] != 0u);
        s_is64 = !any;
    }
    scnt[tid] = 0;
    __syncthreads();
    const int is64 = s_is64;

    // in-degree histogram over dst
    for (int e = tid; e < NE; e += NA) {
        int d = is64 ? (int)ei_raw[2 * (NE + e)] : (int)ei_raw[NE + e];
        atomicAdd(&scnt[d], 1);
    }
    __syncthreads();

    int my = scnt[tid];
    float dinv = rsqrtf((float)(my + 1));   // deg = 1 + in-degree (self loop)
    sdinv[tid]   = dinv;
    g_dinv[tid]  = dinv;
    g_nself[tid] = dinv * dinv;

    // inclusive scan of counts (Hillis-Steele)
    for (int off = 1; off < NA; off <<= 1) {
        int v = (tid >= off) ? scnt[tid - off] : 0;
        __syncthreads();
        scnt[tid] += v;
        __syncthreads();
    }
    int excl = scnt[tid] - my;
    scur[tid]     = excl;
    g_rowptr[tid] = excl;
    if (tid == 0) g_rowptr[NA] = NE;
    __syncthreads();

    // scatter edges into CSR rows keyed by dst
    for (int e = tid; e < NE; e += NA) {
        int s = is64 ? (int)ei_raw[2 * e]        : (int)ei_raw[e];
        int d = is64 ? (int)ei_raw[2 * (NE + e)] : (int)ei_raw[NE + e];
        int pos = atomicAdd(&scur[d], 1);
        g_csrsrc[pos]  = s;
        g_csrnorm[pos] = sdinv[s] * sdinv[d];
    }
}

// ---------- K1: agg_x = A_hat @ x (3 feats), h1 = leaky(agg_x@W1 + b1) ----------
__global__ void k_layer1(const float* __restrict__ x,
                         const float* __restrict__ W1,
                         const float* __restrict__ b1) {
    __shared__ float sx[NA * 3];
    __shared__ float sW1[3 * F1];
    __shared__ float sb1[F1];
    int b = blockIdx.x, tid = threadIdx.x;

    for (int t = tid; t < NA * 3; t += NA) sx[t] = x[(size_t)b * (NA * 3) + t];
    if (tid < 3 * F1) sW1[tid] = W1[tid];
    if (tid < F1)     sb1[tid] = b1[tid];
    __syncthreads();

    int i = tid;
    float ns = g_nself[i];
    float a0 = ns * sx[i * 3 + 0];
    float a1 = ns * sx[i * 3 + 1];
    float a2 = ns * sx[i * 3 + 2];
    int r0 = g_rowptr[i], r1 = g_rowptr[i + 1];
    for (int e = r0; e < r1; e++) {
        int s = g_csrsrc[e];
        float w = g_csrnorm[e];
        a0 += w * sx[s * 3 + 0];
        a1 += w * sx[s * 3 + 1];
        a2 += w * sx[s * 3 + 2];
    }

    float* out = &g_h1[(size_t)b * F1 * NA];
#pragma unroll
    for (int k = 0; k < F1; k++) {
        float v = a0 * sW1[k] + a1 * sW1[F1 + k] + a2 * sW1[2 * F1 + k] + sb1[k];
        out[k * NA + i] = leaky(v);     // coalesced per-k (feature-major)
    }
}

// ---------- K2: t = h1 @ W2 (the big GEMM) ----------
__global__ void __launch_bounds__(512, 1)
k_gemm2(const float* __restrict__ W2) {
    __shared__ float sW2[F1 * F1];
    int mol = blockIdx.x >> 1;
    int i   = ((blockIdx.x & 1) << 9) + threadIdx.x;   // atom

    for (int t = threadIdx.x; t < F1 * F1; t += 512) sW2[t] = W2[t];
    __syncthreads();

    const float* h1 = &g_h1[(size_t)mol * F1 * NA];
    float acc[F1];
#pragma unroll
    for (int j = 0; j < F1; j++) acc[j] = 0.0f;

#pragma unroll 4
    for (int k = 0; k < F1; k++) {
        float a = h1[k * NA + i];                       // coalesced (feature-major)
        const float4* w4 = (const float4*)&sW2[k * F1]; // broadcast LDS.128
#pragma unroll
        for (int j4 = 0; j4 < 16; j4++) {
            float4 w = w4[j4];
            acc[4 * j4 + 0] += a * w.x;
            acc[4 * j4 + 1] += a * w.y;
            acc[4 * j4 + 2] += a * w.z;
            acc[4 * j4 + 3] += a * w.w;
        }
    }

    float4* out = (float4*)&g_t[((size_t)mol * NA + i) * F1];
#pragma unroll
    for (int j4 = 0; j4 < 16; j4++)
        out[j4] = make_float4(acc[4 * j4], acc[4 * j4 + 1],
                              acc[4 * j4 + 2], acc[4 * j4 + 3]);
}

// ---------- K3: h2 = leaky(A_hat@t + b2), mean-pool, project, leaky ----------
__global__ void __launch_bounds__(512, 1)
k_agg_pool_proj(const float* __restrict__ b2,
                const float* __restrict__ Wp,
                const float* __restrict__ bp,
                float* __restrict__ outp) {
    __shared__ float poolw[16][F1];
    __shared__ float gs[F1];
    __shared__ float sb2[F1];
    int b = blockIdx.x, tid = threadIdx.x;
    int warp = tid >> 5, lane = tid & 31;

    // FIX R1: zero ALL 16*64 pool partials (block has only 512 threads)
    for (int t = tid; t < 16 * F1; t += 512) ((float*)poolw)[t] = 0.0f;
    if (tid < F1) sb2[tid] = b2[tid];
    __syncthreads();

    const float* tmol = &g_t[(size_t)b * NA * F1];
    for (int pass = 0; pass < 2; pass++) {
        int i = pass * 512 + tid;                        // atom
        float ns = g_nself[i];
        float acc[F1];
        const float4* self4 = (const float4*)&tmol[(size_t)i * F1];
#pragma unroll
        for (int j4 = 0; j4 < 16; j4++) {
            float4 v = self4[j4];
            acc[4 * j4 + 0] = ns * v.x;
            acc[4 * j4 + 1] = ns * v.y;
            acc[4 * j4 + 2] = ns * v.z;
            acc[4 * j4 + 3] = ns * v.w;
        }
        int r0 = g_rowptr[i], r1 = g_rowptr[i + 1];
        for (int e = r0; e < r1; e++) {
            int s = g_csrsrc[e];
            float w = g_csrnorm[e];
            const float4* row = (const float4*)&tmol[(size_t)s * F1];
#pragma unroll
            for (int j4 = 0; j4 < 16; j4++) {
                float4 v = row[j4];                      // gather: contiguous 256B row
                acc[4 * j4 + 0] += w * v.x;
                acc[4 * j4 + 1] += w * v.y;
                acc[4 * j4 + 2] += w * v.z;
                acc[4 * j4 + 3] += w * v.w;
            }
        }
        // leaky + warp reduce across 32 atoms (lanes), accumulate per-warp partials
#pragma unroll
        for (int j = 0; j < F1; j++) {
            float v = leaky(acc[j] + sb2[j]);
#pragma unroll
            for (int o = 16; o > 0; o >>= 1)
                v += __shfl_xor_sync(0xffffffffu, v, o);
            if (lane == 0) poolw[warp][j] += v;
        }
    }
    __syncthreads();

    if (tid < F1) {
        float s = 0.0f;
#pragma unroll
        for (int w = 0; w < 16; w++) s += poolw[w][tid];
        gs[tid] = s * (1.0f / NA);                       // global mean pool
    }
    __syncthreads();

    if (tid < FP) {
        float v = bp[tid];
#pragma unroll
        for (int k = 0; k < F1; k++) v += gs[k] * Wp[k * FP + tid];
        outp[(size_t)b * FP + tid] = leaky(v);
    }
}

// ---------- launch ----------
extern "C" void kernel_launch(void* const* d_in, const int* in_sizes, int n_in,
                              void* d_out, int out_size) {
    const float* x        = (const float*)d_in[0];
    const unsigned int* e = (const unsigned int*)d_in[1];
    const float* W1       = (const float*)d_in[2];
    const float* b1       = (const float*)d_in[3];
    const float* W2       = (const float*)d_in[4];
    const float* b2       = (const float*)d_in[5];
    const float* Wp       = (const float*)d_in[6];
    const float* bp       = (const float*)d_in[7];
    float* out            = (float*)d_out;

    k_setup<<<1, NA>>>(e);
    k_layer1<<<NB, NA>>>(x, W1, b1);
    k_gemm2<<<NB * 2, 512>>>(W2);
    k_agg_pool_proj<<<NB, 512>>>(b2, Wp, bp, out);
}

// round 3
// speedup vs baseline: 1.4028x; 1.4028x over previous
#include <cuda_runtime.h>

#define NB 256
#define NA 1024
#define NE 8192
#define F1 64
#define FP 128
#define SLOPE 0.01f
#define TILE 128          // atoms per fused-kernel block
#define NTILES (NA / TILE)

// ---------- device scratch (allocation-free: static globals) ----------
__device__ float g_nself[NA];
__device__ int   g_rowptr[NA + 1];
__device__ int   g_csrsrc[NE];
__device__ float g_csrnorm[NE];
// h1 row-major [b][atom][64]: 256B rows for coalesced warp-per-atom gather
__device__ float g_h1[(size_t)NB * NA * F1];
// per-tile pool partials [b*NTILES + tile][64] (deterministic, no float atomics)
__device__ float g_poolpart[(size_t)NB * NTILES * F1];

__device__ __forceinline__ float leaky(float v) {
    return v >= 0.0f ? v : SLOPE * v;
}

// ---------- K0: degrees, norms, CSR build (one block) ----------
__global__ void k_setup(const unsigned int* __restrict__ ei_raw) {
    __shared__ int   scnt[NA];
    __shared__ float sdinv[NA];
    __shared__ int   scur[NA];
    __shared__ int   s_is64;
    int tid = threadIdx.x;

    if (tid == 0) {
        // int64 edge_index has zero high words (values < 1024); int32 does not.
        int any = 0;
        for (int w = 1; w < 64; w += 2) any |= (ei_raw[w] != 0u);
        s_is64 = !any;
    }
    scnt[tid] = 0;
    __syncthreads();
    const int is64 = s_is64;

    for (int e = tid; e < NE; e += NA) {
        int d = is64 ? (int)ei_raw[2 * (NE + e)] : (int)ei_raw[NE + e];
        atomicAdd(&scnt[d], 1);
    }
    __syncthreads();

    int my = scnt[tid];
    float dinv = rsqrtf((float)(my + 1));   // deg = 1 + in-degree (self loop)
    sdinv[tid]   = dinv;
    g_nself[tid] = dinv * dinv;

    for (int off = 1; off < NA; off <<= 1) {   // inclusive scan
        int v = (tid >= off) ? scnt[tid - off] : 0;
        __syncthreads();
        scnt[tid] += v;
        __syncthreads();
    }
    int excl = scnt[tid] - my;
    scur[tid]     = excl;
    g_rowptr[tid] = excl;
    if (tid == 0) g_rowptr[NA] = NE;
    __syncthreads();

    for (int e = tid; e < NE; e += NA) {
        int s = is64 ? (int)ei_raw[2 * e]        : (int)ei_raw[e];
        int d = is64 ? (int)ei_raw[2 * (NE + e)] : (int)ei_raw[NE + e];
        int pos = atomicAdd(&scur[d], 1);
        g_csrsrc[pos]  = s;
        g_csrnorm[pos] = sdinv[s] * sdinv[d];
    }
}

// ---------- K1: h1 = leaky((A_hat@x)@W1 + b1), row-major output ----------
__global__ void k_layer1(const float* __restrict__ x,
                         const float* __restrict__ W1,
                         const float* __restrict__ b1) {
    __shared__ float sx[NA * 3];
    __shared__ float sW1[3 * F1];
    __shared__ float sb1[F1];
    int b = blockIdx.x, tid = threadIdx.x;
    int lane = tid & 31, wbase = tid & ~31;

    for (int t = tid; t < NA * 3; t += NA) sx[t] = x[(size_t)b * (NA * 3) + t];
    if (tid < 3 * F1) sW1[tid] = W1[tid];
    if (tid < F1)     sb1[tid] = b1[tid];
    __syncthreads();

    // thread = atom: aggregate 3 raw features over edges
    float ns = g_nself[tid];
    float a0 = ns * sx[tid * 3 + 0];
    float a1 = ns * sx[tid * 3 + 1];
    float a2 = ns * sx[tid * 3 + 2];
    int r0 = g_rowptr[tid], r1 = g_rowptr[tid + 1];
    for (int e = r0; e < r1; e++) {
        int s = g_csrsrc[e];
        float w = g_csrnorm[e];
        a0 += w * sx[s * 3 + 0];
        a1 += w * sx[s * 3 + 1];
        a2 += w * sx[s * 3 + 2];
    }

    // in-warp transpose: per atom q, lane l emits features 2l, 2l+1 -> coalesced 256B row
    float* h1m = &g_h1[(size_t)b * NA * F1];
    int j = 2 * lane;
#pragma unroll 4
    for (int q = 0; q < 32; q++) {
        float c0 = __shfl_sync(0xffffffffu, a0, q);
        float c1 = __shfl_sync(0xffffffffu, a1, q);
        float c2 = __shfl_sync(0xffffffffu, a2, q);
        float v0 = c0 * sW1[j]     + c1 * sW1[F1 + j]     + c2 * sW1[2 * F1 + j]     + sb1[j];
        float v1 = c0 * sW1[j + 1] + c1 * sW1[F1 + j + 1] + c2 * sW1[2 * F1 + j + 1] + sb1[j + 1];
        float2 o = make_float2(leaky(v0), leaky(v1));
        ((float2*)&h1m[(size_t)(wbase + q) * F1])[lane] = o;
    }
}

// ---------- K2: fused  agg = A_hat@h1 ; h2 = leaky(agg@W2+b2) ; tile pool ----------
#define AGG_PITCH 66   // 66*4B rows: float2-aligned, 2-way LDS conflict max
__global__ void __launch_bounds__(512)
k_fused(const float* __restrict__ W2, const float* __restrict__ b2) {
    __shared__ float sagg[TILE * AGG_PITCH];      // 33792 B
    __shared__ float pool_sm[16][16];             // [warp][j-chunk]
    int b    = blockIdx.x >> 3;
    int tile = blockIdx.x & 7;
    int base = tile * TILE;
    int tid = threadIdx.x, wid = tid >> 5, lane = tid & 31;

    const float* h1m = &g_h1[(size_t)b * NA * F1];

    // ---- Phase A: warp-per-atom gather, lane l holds features 2l,2l+1 ----
    for (int a = wid; a < TILE; a += 16) {
        int atom = base + a;
        float ns = g_nself[atom];
        float2 v = ((const float2*)&h1m[(size_t)atom * F1])[lane];
        float ax = ns * v.x, ay = ns * v.y;
        int r0 = g_rowptr[atom], r1 = g_rowptr[atom + 1];
        for (int e = r0; e < r1; e++) {
            int s   = g_csrsrc[e];
            float w = g_csrnorm[e];
            float2 rv = ((const float2*)&h1m[(size_t)s * F1])[lane];  // coalesced 256B row
            ax += w * rv.x;
            ay += w * rv.y;
        }
        ((float2*)&sagg[a * AGG_PITCH])[lane] = make_float2(ax, ay);
    }
    __syncthreads();

    // ---- Phase B: GEMM agg@W2, warp = 32 atoms x 16 output features ----
    int ag = wid & 3;                 // atom group
    int jr = wid >> 2;                // feature range
    int a  = ag * 32 + lane;          // atom within tile
    int j0 = jr * 16;

    float acc[16];
#pragma unroll
    for (int q = 0; q < 16; q++) acc[q] = 0.0f;

    const float* aggrow = &sagg[a * AGG_PITCH];
#pragma unroll 4
    for (int k = 0; k < F1; k++) {
        float av = aggrow[k];
        const float4* w4 = (const float4*)&W2[k * F1 + j0];   // broadcast, L1-resident
        float4 w0 = __ldg(&w4[0]), w1 = __ldg(&w4[1]);
        float4 w2v = __ldg(&w4[2]), w3 = __ldg(&w4[3]);
        acc[0]  += av * w0.x;  acc[1]  += av * w0.y;  acc[2]  += av * w0.z;  acc[3]  += av * w0.w;
        acc[4]  += av * w1.x;  acc[5]  += av * w1.y;  acc[6]  += av * w1.z;  acc[7]  += av * w1.w;
        acc[8]  += av * w2v.x; acc[9]  += av * w2v.y; acc[10] += av * w2v.z; acc[11] += av * w2v.w;
        acc[12] += av * w3.x;  acc[13] += av * w3.y;  acc[14] += av * w3.z;  acc[15] += av * w3.w;
    }

    // bias + leaky + shfl pool-reduce across the warp's 32 atoms
    const float4* b4 = (const float4*)&b2[j0];
    float4 bb[4] = {__ldg(&b4[0]), __ldg(&b4[1]), __ldg(&b4[2]), __ldg(&b4[3])};
    float* bbf = (float*)bb;
#pragma unroll
    for (int q = 0; q < 16; q++) {
        float v = leaky(acc[q] + bbf[q]);
#pragma unroll
        for (int o = 16; o > 0; o >>= 1)
            v += __shfl_xor_sync(0xffffffffu, v, o);
        if (lane == 0) pool_sm[wid][q] = v;
    }
    __syncthreads();

    // combine 4 atom-groups per feature, write tile partial
    if (tid < F1) {
        int jjr = tid >> 4, jj = tid & 15;
        float s = pool_sm[jjr * 4 + 0][jj] + pool_sm[jjr * 4 + 1][jj]
                + pool_sm[jjr * 4 + 2][jj] + pool_sm[jjr * 4 + 3][jj];
        g_poolpart[(size_t)blockIdx.x * F1 + tid] = s;
    }
}

// ---------- K3: reduce tile partials, mean, project, leaky ----------
__global__ void k_final(const float* __restrict__ Wp,
                        const float* __restrict__ bp,
                        float* __restrict__ outp) {
    __shared__ float gs[F1];
    int b = blockIdx.x, tid = threadIdx.x;
    if (tid < F1) {
        float s = 0.0f;
#pragma unroll
        for (int t = 0; t < NTILES; t++)
            s += g_poolpart[(size_t)(b * NTILES + t) * F1 + tid];
        gs[tid] = s * (1.0f / NA);
    }
    __syncthreads();
    if (tid < FP) {
        float v = bp[tid];
#pragma unroll
        for (int k = 0; k < F1; k++) v += gs[k] * Wp[k * FP + tid];
        outp[(size_t)b * FP + tid] = leaky(v);
    }
}

// ---------- launch ----------
extern "C" void kernel_launch(void* const* d_in, const int* in_sizes, int n_in,
                              void* d_out, int out_size) {
    const float* x        = (const float*)d_in[0];
    const unsigned int* e = (const unsigned int*)d_in[1];
    const float* W1       = (const float*)d_in[2];
    const float* b1       = (const float*)d_in[3];
    const float* W2       = (const float*)d_in[4];
    const float* b2       = (const float*)d_in[5];
    const float* Wp       = (const float*)d_in[6];
    const float* bp       = (const float*)d_in[7];
    float* out            = (float*)d_out;

    k_setup<<<1, NA>>>(e);
    k_layer1<<<NB, NA>>>(x, W1, b1);
    k_fused<<<NB * NTILES, 512>>>(W2, b2);
    k_final<<<NB, FP>>>(Wp, bp, out);
}

// round 5
// speedup vs baseline: 1.7486x; 1.2465x over previous
#include <cuda_runtime.h>

#define NB 256
#define NA 1024
#define NE 8192
#define F1 64
#define FP 128
#define SLOPE 0.01f
#define TILE 128          // atoms per fused-kernel block
#define NTILES (NA / TILE)

// ---------- device scratch (allocation-free: static globals) ----------
__device__ float g_nself[NA];
__device__ int   g_rowptr[NA + 1];
__device__ int   g_csrsrc[NE];
__device__ float g_csrnorm[NE];
// h1 row-major [b][atom][64]: 256B rows for coalesced warp-per-atom gather
__device__ float g_h1[(size_t)NB * NA * F1];
// per-tile pool partials [b*NTILES + tile][64] (deterministic, no float atomics)
__device__ float g_poolpart[(size_t)NB * NTILES * F1];

__device__ __forceinline__ float leaky(float v) {
    return v >= 0.0f ? v : SLOPE * v;
}

// packed 2-wide fp32 FMA (Blackwell f32x2 pipe; ptxas never auto-fuses this)
union F2U { float2 f; unsigned long long u; };
__device__ __forceinline__ void ffma2_acc(float2& acc, float2 a, float2 b) {
    F2U ua, ub, uc;
    ua.f = a; ub.f = b; uc.f = acc;
    asm("fma.rn.f32x2 %0, %1, %2, %0;" : "+l"(uc.u) : "l"(ua.u), "l"(ub.u));
    acc = uc.f;
}

// ---------- K0: degrees, norms, CSR build (one block) ----------
__global__ void k_setup(const unsigned int* __restrict__ ei_raw) {
    __shared__ int   scnt[NA];
    __shared__ float sdinv[NA];
    __shared__ int   scur[NA];
    __shared__ int   s_is64;
    int tid = threadIdx.x;

    if (tid == 0) {
        // int64 edge_index has zero high words (values < 1024); int32 does not.
        int any = 0;
        for (int w = 1; w < 64; w += 2) any |= (ei_raw[w] != 0u);
        s_is64 = !any;
    }
    scnt[tid] = 0;
    __syncthreads();
    const int is64 = s_is64;

    for (int e = tid; e < NE; e += NA) {
        int d = is64 ? (int)ei_raw[2 * (NE + e)] : (int)ei_raw[NE + e];
        atomicAdd(&scnt[d], 1);
    }
    __syncthreads();

    int my = scnt[tid];
    float dinv = rsqrtf((float)(my + 1));   // deg = 1 + in-degree (self loop)
    sdinv[tid]   = dinv;
    g_nself[tid] = dinv * dinv;

    for (int off = 1; off < NA; off <<= 1) {   // inclusive scan
        int v = (tid >= off) ? scnt[tid - off] : 0;
        __syncthreads();
        scnt[tid] += v;
        __syncthreads();
    }
    int excl = scnt[tid] - my;
    scur[tid]     = excl;
    g_rowptr[tid] = excl;
    if (tid == 0) g_rowptr[NA] = NE;
    __syncthreads();

    for (int e = tid; e < NE; e += NA) {
        int s = is64 ? (int)ei_raw[2 * e]        : (int)ei_raw[e];
        int d = is64 ? (int)ei_raw[2 * (NE + e)] : (int)ei_raw[NE + e];
        int pos = atomicAdd(&scur[d], 1);
        g_csrsrc[pos]  = s;
        g_csrnorm[pos] = sdinv[s] * sdinv[d];
    }
}

// ---------- K1: h1 = leaky((A_hat@x)@W1 + b1), row-major output ----------
__global__ void k_layer1(const float* __restrict__ x,
                         const float* __restrict__ W1,
                         const float* __restrict__ b1) {
    __shared__ float sx[NA * 3];
    __shared__ float sW1[3 * F1];
    __shared__ float sb1[F1];
    int b = blockIdx.x, tid = threadIdx.x;
    int lane = tid & 31, wbase = tid & ~31;

    for (int t = tid; t < NA * 3; t += NA) sx[t] = x[(size_t)b * (NA * 3) + t];
    if (tid < 3 * F1) sW1[tid] = W1[tid];
    if (tid < F1)     sb1[tid] = b1[tid];
    __syncthreads();

    // thread = atom: aggregate 3 raw features over edges
    float ns = g_nself[tid];
    float a0 = ns * sx[tid * 3 + 0];
    float a1 = ns * sx[tid * 3 + 1];
    float a2 = ns * sx[tid * 3 + 2];
    int r0 = g_rowptr[tid], r1 = g_rowptr[tid + 1];
#pragma unroll 4
    for (int e = r0; e < r1; e++) {
        int s = g_csrsrc[e];
        float w = g_csrnorm[e];
        a0 += w * sx[s * 3 + 0];
        a1 += w * sx[s * 3 + 1];
        a2 += w * sx[s * 3 + 2];
    }

    // in-warp transpose: per atom q, lane l emits features 2l, 2l+1 -> coalesced 256B row
    float* h1m = &g_h1[(size_t)b * NA * F1];
    int j = 2 * lane;
#pragma unroll 4
    for (int q = 0; q < 32; q++) {
        float c0 = __shfl_sync(0xffffffffu, a0, q);
        float c1 = __shfl_sync(0xffffffffu, a1, q);
        float c2 = __shfl_sync(0xffffffffu, a2, q);
        float v0 = c0 * sW1[j]     + c1 * sW1[F1 + j]     + c2 * sW1[2 * F1 + j]     + sb1[j];
        float v1 = c0 * sW1[j + 1] + c1 * sW1[F1 + j + 1] + c2 * sW1[2 * F1 + j + 1] + sb1[j + 1];
        float2 o = make_float2(leaky(v0), leaky(v1));
        ((float2*)&h1m[(size_t)(wbase + q) * F1])[lane] = o;
    }
}

// ---------- K2: fused  agg = A_hat@h1 ; h2 = leaky(agg@W2+b2) ; tile pool ----------
#define AGG_PITCH 66   // float2-aligned, max 2-way LDS conflict
#define SMEM_AGG   0                               // TILE*AGG_PITCH floats = 8448
#define SMEM_W2    (TILE * AGG_PITCH)              // 4096 floats
#define SMEM_POOL  (SMEM_W2 + F1 * F1)             // 256 floats
#define SMEM_FUSED_BYTES ((SMEM_POOL + 16 * 16) * 4)   // 51200 B

__global__ void __launch_bounds__(512, 2)
k_fused(const float* __restrict__ W2, const float* __restrict__ b2) {
    extern __shared__ float smem[];
    float* sagg    = smem + SMEM_AGG;
    float* sW2     = smem + SMEM_W2;
    float* pool_sm = smem + SMEM_POOL;            // [warp][16]
    int b    = blockIdx.x >> 3;
    int tile = blockIdx.x & 7;
    int base = tile * TILE;
    int tid = threadIdx.x, wid = tid >> 5, lane = tid & 31;

    const float* h1m = &g_h1[(size_t)b * NA * F1];

    for (int t = tid; t < F1 * F1; t += 512) sW2[t] = W2[t];

    // ---- Phase A: warp-per-atom gather, lane l holds features 2l,2l+1 ----
    for (int a = wid; a < TILE; a += 16) {
        int atom = base + a;
        float ns = g_nself[atom];
        float2 v = ((const float2*)&h1m[(size_t)atom * F1])[lane];
        float ax = ns * v.x, ay = ns * v.y;
        int r0 = g_rowptr[atom], r1 = g_rowptr[atom + 1];
#pragma unroll 4
        for (int e = r0; e < r1; e++) {
            int s   = g_csrsrc[e];
            float w = g_csrnorm[e];
            float2 rv = ((const float2*)&h1m[(size_t)s * F1])[lane];  // coalesced 256B row
            ax += w * rv.x;
            ay += w * rv.y;
        }
        ((float2*)&sagg[a * AGG_PITCH])[lane] = make_float2(ax, ay);
    }
    __syncthreads();

    // ---- Phase B: GEMM agg@W2 with packed f32x2 FFMA ----
    // warp = (atom group ag of 32 atoms) x (feature range jr of 16 j)
    int ag = wid & 3;
    int jr = wid >> 2;
    int a  = ag * 32 + lane;
    int j0 = jr * 16;

    float2 acc2[8];
#pragma unroll
    for (int q = 0; q < 8; q++) acc2[q] = make_float2(0.0f, 0.0f);

    const float* aggrow = &sagg[a * AGG_PITCH];
#pragma unroll 4
    for (int k = 0; k < F1; k++) {
        float av = aggrow[k];
        float2 ad = make_float2(av, av);
        const float4* w4 = (const float4*)&sW2[k * F1 + j0];  // broadcast LDS.128
        float4 wa = w4[0], wb = w4[1], wc = w4[2], wd = w4[3];
        ffma2_acc(acc2[0], ad, make_float2(wa.x, wa.y));
        ffma2_acc(acc2[1], ad, make_float2(wa.z, wa.w));
        ffma2_acc(acc2[2], ad, make_float2(wb.x, wb.y));
        ffma2_acc(acc2[3], ad, make_float2(wb.z, wb.w));
        ffma2_acc(acc2[4], ad, make_float2(wc.x, wc.y));
        ffma2_acc(acc2[5], ad, make_float2(wc.z, wc.w));
        ffma2_acc(acc2[6], ad, make_float2(wd.x, wd.y));
        ffma2_acc(acc2[7], ad, make_float2(wd.z, wd.w));
    }

    // bias + leaky + shfl pool-reduce across the warp's 32 atoms
    const float* accf = (const float*)acc2;
#pragma unroll
    for (int q = 0; q < 16; q++) {
        float v = leaky(accf[q] + b2[j0 + q]);
#pragma unroll
        for (int o = 16; o > 0; o >>= 1)
            v += __shfl_xor_sync(0xffffffffu, v, o);
        if (lane == 0) pool_sm[wid * 16 + q] = v;
    }
    __syncthreads();

    // combine 4 atom-groups per feature, write tile partial
    if (tid < F1) {
        int jjr = tid >> 4, jj = tid & 15;
        float s = pool_sm[(jjr * 4 + 0) * 16 + jj] + pool_sm[(jjr * 4 + 1) * 16 + jj]
                + pool_sm[(jjr * 4 + 2) * 16 + jj] + pool_sm[(jjr * 4 + 3) * 16 + jj];
        g_poolpart[(size_t)blockIdx.x * F1 + tid] = s;
    }
}

// ---------- K3: reduce tile partials, mean, project, leaky ----------
__global__ void k_final(const float* __restrict__ Wp,
                        const float* __restrict__ bp,
                        float* __restrict__ outp) {
    __shared__ float gs[F1];
    int b = blockIdx.x, tid = threadIdx.x;
    if (tid < F1) {
        float s = 0.0f;
#pragma unroll
        for (int t = 0; t < NTILES; t++)
            s += g_poolpart[(size_t)(b * NTILES + t) * F1 + tid];
        gs[tid] = s * (1.0f / NA);
    }
    __syncthreads();
    if (tid < FP) {
        float v = bp[tid];
#pragma unroll
        for (int k = 0; k < F1; k++) v += gs[k] * Wp[k * FP + tid];
        outp[(size_t)b * FP + tid] = leaky(v);
    }
}

// ---------- launch ----------
extern "C" void kernel_launch(void* const* d_in, const int* in_sizes, int n_in,
                              void* d_out, int out_size) {
    const float* x        = (const float*)d_in[0];
    const unsigned int* e = (const unsigned int*)d_in[1];
    const float* W1       = (const float*)d_in[2];
    const float* b1       = (const float*)d_in[3];
    const float* W2       = (const float*)d_in[4];
    const float* b2       = (const float*)d_in[5];
    const float* Wp       = (const float*)d_in[6];
    const float* bp       = (const float*)d_in[7];
    float* out            = (float*)d_out;

    // idempotent, host-side attribute set (not a stream op; capture-safe)
    cudaFuncSetAttribute(k_fused, cudaFuncAttributeMaxDynamicSharedMemorySize,
                         SMEM_FUSED_BYTES);

    k_setup<<<1, NA>>>(e);
    k_layer1<<<NB, NA>>>(x, W1, b1);
    k_fused<<<NB * NTILES, 512, SMEM_FUSED_BYTES>>>(W2, b2);
    k_final<<<NB, FP>>>(Wp, bp, out);
}

// round 7
// speedup vs baseline: 2.5380x; 1.4514x over previous
#include <cuda_runtime.h>
#include <cuda_fp16.h>
#include <cstdint>

#define NB 256
#define NA 1024
#define NE 8192
#define F1 64
#define FP 128
#define SLOPE 0.01f
#define TILE 128          // atoms per fused-kernel block
#define NTILES (NA / TILE)

// ---------- device scratch (allocation-free: static globals) ----------
__device__ float g_nself[NA];
__device__ int   g_rowptr[NA + 1];
__device__ int   g_csrsrc[NE];
__device__ float g_csrnorm[NE];
// h1 row-major [b][atom][64]: 256B rows for coalesced warp-per-atom gather
__device__ float g_h1[(size_t)NB * NA * F1];
// per-tile pool partials [b*NTILES + tile][64] (deterministic, no float atomics)
__device__ float g_poolpart[(size_t)NB * NTILES * F1];

__device__ __forceinline__ float leaky(float v) {
    return v >= 0.0f ? v : SLOPE * v;
}

__device__ __forceinline__ unsigned smem_u32(const void* p) {
    return (unsigned)__cvta_generic_to_shared(p);
}
__device__ __forceinline__ void ldsm_x4(unsigned addr, unsigned& r0, unsigned& r1,
                                        unsigned& r2, unsigned& r3) {
    asm volatile("ldmatrix.sync.aligned.m8n8.x4.shared.b16 {%0,%1,%2,%3}, [%4];"
                 : "=r"(r0), "=r"(r1), "=r"(r2), "=r"(r3) : "r"(addr));
}
__device__ __forceinline__ void ldsm_x4t(unsigned addr, unsigned& r0, unsigned& r1,
                                         unsigned& r2, unsigned& r3) {
    asm volatile("ldmatrix.sync.aligned.m8n8.x4.trans.shared.b16 {%0,%1,%2,%3}, [%4];"
                 : "=r"(r0), "=r"(r1), "=r"(r2), "=r"(r3) : "r"(addr));
}
__device__ __forceinline__ void mma16816(float* c, unsigned a0, unsigned a1,
                                         unsigned a2, unsigned a3,
                                         unsigned b0, unsigned b1) {
    asm volatile(
        "mma.sync.aligned.m16n8k16.row.col.f32.f16.f16.f32 "
        "{%0,%1,%2,%3}, {%4,%5,%6,%7}, {%8,%9}, {%0,%1,%2,%3};"
        : "+f"(c[0]), "+f"(c[1]), "+f"(c[2]), "+f"(c[3])
        : "r"(a0), "r"(a1), "r"(a2), "r"(a3), "r"(b0), "r"(b1));
}

// ---------- K0: degrees, norms, CSR build (one block) ----------
__global__ void k_setup(const unsigned int* __restrict__ ei_raw) {
    __shared__ int   scnt[NA];
    __shared__ float sdinv[NA];
    __shared__ int   scur[NA];
    __shared__ int   s_is64;
    int tid = threadIdx.x;

    if (tid == 0) {
        // int64 edge_index has zero high words (values < 1024); int32 does not.
        int any = 0;
        for (int w = 1; w < 64; w += 2) any |= (ei_raw[w] != 0u);
        s_is64 = !any;
    }
    scnt[tid] = 0;
    __syncthreads();
    const int is64 = s_is64;

    for (int e = tid; e < NE; e += NA) {
        int d = is64 ? (int)ei_raw[2 * (NE + e)] : (int)ei_raw[NE + e];
        atomicAdd(&scnt[d], 1);
    }
    __syncthreads();

    int my = scnt[tid];
    float dinv = rsqrtf((float)(my + 1));   // deg = 1 + in-degree (self loop)
    sdinv[tid]   = dinv;
    g_nself[tid] = dinv * dinv;

    for (int off = 1; off < NA; off <<= 1) {   // inclusive scan
        int v = (tid >= off) ? scnt[tid - off] : 0;
        __syncthreads();
        scnt[tid] += v;
        __syncthreads();
    }
    int excl = scnt[tid] - my;
    scur[tid]     = excl;
    g_rowptr[tid] = excl;
    if (tid == 0) g_rowptr[NA] = NE;
    __syncthreads();

    for (int e = tid; e < NE; e += NA) {
        int s = is64 ? (int)ei_raw[2 * e]        : (int)ei_raw[e];
        int d = is64 ? (int)ei_raw[2 * (NE + e)] : (int)ei_raw[NE + e];
        int pos = atomicAdd(&scur[d], 1);
        g_csrsrc[pos]  = s;
        g_csrnorm[pos] = sdinv[s] * sdinv[d];
    }
}

// ---------- K1: h1 = leaky((A_hat@x)@W1 + b1), row-major fp32 output ----------
__global__ void k_layer1(const float* __restrict__ x,
                         const float* __restrict__ W1,
                         const float* __restrict__ b1) {
    __shared__ float sx[NA * 3];
    __shared__ float sW1[3 * F1];
    __shared__ float sb1[F1];
    int b = blockIdx.x, tid = threadIdx.x;
    int lane = tid & 31, wbase = tid & ~31;

    for (int t = tid; t < NA * 3; t += NA) sx[t] = x[(size_t)b * (NA * 3) + t];
    if (tid < 3 * F1) sW1[tid] = W1[tid];
    if (tid < F1)     sb1[tid] = b1[tid];
    __syncthreads();

    // thread = atom: aggregate 3 raw features over edges
    float ns = g_nself[tid];
    float a0 = ns * sx[tid * 3 + 0];
    float a1 = ns * sx[tid * 3 + 1];
    float a2 = ns * sx[tid * 3 + 2];
    int r0 = g_rowptr[tid], r1 = g_rowptr[tid + 1];
#pragma unroll 4
    for (int e = r0; e < r1; e++) {
        int s = g_csrsrc[e];
        float w = g_csrnorm[e];
        a0 += w * sx[s * 3 + 0];
        a1 += w * sx[s * 3 + 1];
        a2 += w * sx[s * 3 + 2];
    }

    // in-warp transpose: per atom q, lane l emits features 2l, 2l+1 -> coalesced 256B row
    float* h1m = &g_h1[(size_t)b * NA * F1];
    int j = 2 * lane;
#pragma unroll 4
    for (int q = 0; q < 32; q++) {
        float c0 = __shfl_sync(0xffffffffu, a0, q);
        float c1 = __shfl_sync(0xffffffffu, a1, q);
        float c2 = __shfl_sync(0xffffffffu, a2, q);
        float v0 = c0 * sW1[j]     + c1 * sW1[F1 + j]     + c2 * sW1[2 * F1 + j]     + sb1[j];
        float v1 = c0 * sW1[j + 1] + c1 * sW1[F1 + j + 1] + c2 * sW1[2 * F1 + j + 1] + sb1[j + 1];
        float2 o = make_float2(leaky(v0), leaky(v1));
        ((float2*)&h1m[(size_t)(wbase + q) * F1])[lane] = o;
    }
}

// ---------- K2: fused  agg = A_hat@h1 ; h2 = leaky(agg@W2+b2) via HMMA ; pool ----------
#define AGG_PITCH 72   // halfs; 144B row stride -> ldmatrix conflict-free (4r mod 32)
__global__ void __launch_bounds__(512, 2)
k_fused(const float* __restrict__ W2, const float* __restrict__ b2) {
    __shared__ __half saggh[TILE * AGG_PITCH];    // 18432 B
    __shared__ __half sW2h[F1 * AGG_PITCH];       // 9216 B
    __shared__ float  pool_sm[16][32];            // 2048 B
    int b    = blockIdx.x >> 3;
    int tile = blockIdx.x & 7;
    int base = tile * TILE;
    int tid = threadIdx.x, wid = tid >> 5, lane = tid & 31;

    const float* h1m = &g_h1[(size_t)b * NA * F1];

    // stage W2 as fp16, padded pitch
    for (int t = tid; t < F1 * F1; t += 512) {
        int k = t >> 6, j = t & 63;
        sW2h[k * AGG_PITCH + j] = __float2half_rn(W2[t]);
    }

    // ---- Phase A: warp-per-atom gather (fp32), write fp16 agg rows ----
    for (int a = wid; a < TILE; a += 16) {
        int atom = base + a;
        float ns = g_nself[atom];
        float2 v = ((const float2*)&h1m[(size_t)atom * F1])[lane];
        float ax = ns * v.x, ay = ns * v.y;
        int r0 = g_rowptr[atom], r1 = g_rowptr[atom + 1];
#pragma unroll 4
        for (int e = r0; e < r1; e++) {
            int s   = g_csrsrc[e];
            float w = g_csrnorm[e];
            float2 rv = ((const float2*)&h1m[(size_t)s * F1])[lane];  // coalesced 256B row
            ax += w * rv.x;
            ay += w * rv.y;
        }
        ((__half2*)&saggh[a * AGG_PITCH])[lane] = __floats2half2_rn(ax, ay);
    }
    __syncthreads();

    // ---- Phase B: 128x64x64 GEMM on tensor cores (m16n8k16) ----
    // warp tile: m16 x n32.  wid = mtile*2 + nhalf
    int m0 = (wid >> 1) * 16;
    int j0 = (wid & 1) * 32;
    int grp = lane >> 3, lr = lane & 7;

    float c[4][4];
#pragma unroll
    for (int q = 0; q < 4; q++)
#pragma unroll
        for (int r = 0; r < 4; r++) c[q][r] = 0.0f;

    unsigned sagg_b = smem_u32(saggh);
    unsigned sw2_b  = smem_u32(sW2h);

#pragma unroll
    for (int kc = 0; kc < F1; kc += 16) {
        int arow = m0 + (grp & 1) * 8 + lr;
        int acol = kc + (grp >> 1) * 8;
        unsigned a0, a1, a2, a3;
        ldsm_x4(sagg_b + (arow * AGG_PITCH + acol) * 2, a0, a1, a2, a3);

        int brow = kc + (grp & 1) * 8 + lr;
#pragma unroll
        for (int p = 0; p < 2; p++) {
            int bcol = j0 + p * 16 + (grp >> 1) * 8;
            unsigned b0, b1, b2r, b3;
            ldsm_x4t(sw2_b + (brow * AGG_PITCH + bcol) * 2, b0, b1, b2r, b3);
            mma16816(c[2 * p],     a0, a1, a2, a3, b0,  b1);
            mma16816(c[2 * p + 1], a0, a1, a2, a3, b2r, b3);
        }
    }

    // ---- bias + leaky + pool-reduce over the warp's 16 atom rows ----
    int t4 = lane & 3;
#pragma unroll
    for (int nt = 0; nt < 4; nt++) {
        int jb = j0 + nt * 8 + 2 * t4;
        float bb0 = __ldg(&b2[jb]), bb1 = __ldg(&b2[jb + 1]);
        float s0 = leaky(c[nt][0] + bb0) + leaky(c[nt][2] + bb0);
        float s1 = leaky(c[nt][1] + bb1) + leaky(c[nt][3] + bb1);
#pragma unroll
        for (int o = 4; o < 32; o <<= 1) {
            s0 += __shfl_xor_sync(0xffffffffu, s0, o);
            s1 += __shfl_xor_sync(0xffffffffu, s1, o);
        }
        if (lane < 4) {
            pool_sm[wid][nt * 8 + 2 * t4]     = s0;
            pool_sm[wid][nt * 8 + 2 * t4 + 1] = s1;
        }
    }
    __syncthreads();

    // combine 8 m-tile warps per feature, write tile partial
    if (tid < F1) {
        int nh = tid >> 5, cw = tid & 31;
        float s = 0.0f;
#pragma unroll
        for (int m = 0; m < 8; m++) s += pool_sm[m * 2 + nh][cw];
        g_poolpart[(size_t)blockIdx.x * F1 + tid] = s;
    }
}

// ---------- K3: reduce tile partials, mean, project, leaky ----------
__global__ void k_final(const float* __restrict__ Wp,
                        const float* __restrict__ bp,
                        float* __restrict__ outp) {
    __shared__ float gs[F1];
    int b = blockIdx.x, tid = threadIdx.x;
    if (tid < F1) {
        float s = 0.0f;
#pragma unroll
        for (int t = 0; t < NTILES; t++)
            s += g_poolpart[(size_t)(b * NTILES + t) * F1 + tid];
        gs[tid] = s * (1.0f / NA);
    }
    __syncthreads();
    if (tid < FP) {
        float v = bp[tid];
#pragma unroll
        for (int k = 0; k < F1; k++) v += gs[k] * Wp[k * FP + tid];
        outp[(size_t)b * FP + tid] = leaky(v);
    }
}

// ---------- launch ----------
extern "C" void kernel_launch(void* const* d_in, const int* in_sizes, int n_in,
                              void* d_out, int out_size) {
    const float* x        = (const float*)d_in[0];
    const unsigned int* e = (const unsigned int*)d_in[1];
    const float* W1       = (const float*)d_in[2];
    const float* b1       = (const float*)d_in[3];
    const float* W2       = (const float*)d_in[4];
    const float* b2       = (const float*)d_in[5];
    const float* Wp       = (const float*)d_in[6];
    const float* bp       = (const float*)d_in[7];
    float* out            = (float*)d_out;

    k_setup<<<1, NA>>>(e);
    k_layer1<<<NB, NA>>>(x, W1, b1);
    k_fused<<<NB * NTILES, 512>>>(W2, b2);
    k_final<<<NB, FP>>>(Wp, bp, out);
}

// round 8
// speedup vs baseline: 2.5720x; 1.0134x over previous
#include <cuda_runtime.h>
#include <cuda_fp16.h>
#include <cstdint>

#define NB 256
#define NA 1024
#define NE 8192
#define F1 64
#define FP 128
#define SLOPE 0.01f
#define TILE 128
#define NTILES (NA / TILE)

// ---------- device scratch (allocation-free: static globals) ----------
__device__ float  g_nself[NA];
__device__ int    g_rowptr[NA + 1];
__device__ int    g_csrsrc[NE];
__device__ float  g_csrnorm[NE];
// h1 fp16 row-major [b][atom][64]: 128B rows
__device__ __half g_h1[(size_t)NB * NA * F1];

__device__ __forceinline__ float leaky(float v) {
    return v >= 0.0f ? v : SLOPE * v;
}

__device__ __forceinline__ unsigned smem_u32(const void* p) {
    return (unsigned)__cvta_generic_to_shared(p);
}
__device__ __forceinline__ void ldsm_x4(unsigned addr, unsigned& r0, unsigned& r1,
                                        unsigned& r2, unsigned& r3) {
    asm volatile("ldmatrix.sync.aligned.m8n8.x4.shared.b16 {%0,%1,%2,%3}, [%4];"
                 : "=r"(r0), "=r"(r1), "=r"(r2), "=r"(r3) : "r"(addr));
}
__device__ __forceinline__ void ldsm_x4t(unsigned addr, unsigned& r0, unsigned& r1,
                                         unsigned& r2, unsigned& r3) {
    asm volatile("ldmatrix.sync.aligned.m8n8.x4.trans.shared.b16 {%0,%1,%2,%3}, [%4];"
                 : "=r"(r0), "=r"(r1), "=r"(r2), "=r"(r3) : "r"(addr));
}
__device__ __forceinline__ void mma16816(float* c, unsigned a0, unsigned a1,
                                         unsigned a2, unsigned a3,
                                         unsigned b0, unsigned b1) {
    asm volatile(
        "mma.sync.aligned.m16n8k16.row.col.f32.f16.f16.f32 "
        "{%0,%1,%2,%3}, {%4,%5,%6,%7}, {%8,%9}, {%0,%1,%2,%3};"
        : "+f"(c[0]), "+f"(c[1]), "+f"(c[2]), "+f"(c[3])
        : "r"(a0), "r"(a1), "r"(a2), "r"(a3), "r"(b0), "r"(b1));
}

// ---------- K0: degrees, norms, CSR build (one block) ----------
__global__ void k_setup(const unsigned int* __restrict__ ei_raw) {
    __shared__ int   scnt[NA];
    __shared__ float sdinv[NA];
    __shared__ int   scur[NA];
    __shared__ int   s_is64;
    int tid = threadIdx.x;

    if (tid == 0) {
        // int64 edge_index has zero high words (values < 1024); int32 does not.
        int any = 0;
        for (int w = 1; w < 64; w += 2) any |= (ei_raw[w] != 0u);
        s_is64 = !any;
    }
    scnt[tid] = 0;
    __syncthreads();
    const int is64 = s_is64;

    for (int e = tid; e < NE; e += NA) {
        int d = is64 ? (int)ei_raw[2 * (NE + e)] : (int)ei_raw[NE + e];
        atomicAdd(&scnt[d], 1);
    }
    __syncthreads();

    int my = scnt[tid];
    float dinv = rsqrtf((float)(my + 1));   // deg = 1 + in-degree (self loop)
    sdinv[tid]   = dinv;
    g_nself[tid] = dinv * dinv;

    for (int off = 1; off < NA; off <<= 1) {   // inclusive scan
        int v = (tid >= off) ? scnt[tid - off] : 0;
        __syncthreads();
        scnt[tid] += v;
        __syncthreads();
    }
    int excl = scnt[tid] - my;
    scur[tid]     = excl;
    g_rowptr[tid] = excl;
    if (tid == 0) g_rowptr[NA] = NE;
    __syncthreads();

    for (int e = tid; e < NE; e += NA) {
        int s = is64 ? (int)ei_raw[2 * e]        : (int)ei_raw[e];
        int d = is64 ? (int)ei_raw[2 * (NE + e)] : (int)ei_raw[NE + e];
        int pos = atomicAdd(&scur[d], 1);
        g_csrsrc[pos]  = s;
        g_csrnorm[pos] = sdinv[s] * sdinv[d];
    }
}

// ---------- K1: h1 = leaky((A_hat@x)@W1 + b1), fp16 row-major output ----------
__global__ void k_layer1(const float* __restrict__ x,
                         const float* __restrict__ W1,
                         const float* __restrict__ b1) {
    __shared__ float sx[NA * 3];
    __shared__ float sW1[3 * F1];
    __shared__ float sb1[F1];
    int b = blockIdx.x, tid = threadIdx.x;
    int lane = tid & 31, wbase = tid & ~31;

    for (int t = tid; t < NA * 3; t += NA) sx[t] = x[(size_t)b * (NA * 3) + t];
    if (tid < 3 * F1) sW1[tid] = W1[tid];
    if (tid < F1)     sb1[tid] = b1[tid];
    __syncthreads();

    // thread = atom: aggregate 3 raw features over edges
    float ns = g_nself[tid];
    float a0 = ns * sx[tid * 3 + 0];
    float a1 = ns * sx[tid * 3 + 1];
    float a2 = ns * sx[tid * 3 + 2];
    int r0 = g_rowptr[tid], r1 = g_rowptr[tid + 1];
#pragma unroll 4
    for (int e = r0; e < r1; e++) {
        int s = g_csrsrc[e];
        float w = g_csrnorm[e];
        a0 += w * sx[s * 3 + 0];
        a1 += w * sx[s * 3 + 1];
        a2 += w * sx[s * 3 + 2];
    }

    // in-warp transpose: per atom q, lane l emits features 2l, 2l+1 -> coalesced 128B row
    __half* h1m = &g_h1[(size_t)b * NA * F1];
    int j = 2 * lane;
#pragma unroll 4
    for (int q = 0; q < 32; q++) {
        float c0 = __shfl_sync(0xffffffffu, a0, q);
        float c1 = __shfl_sync(0xffffffffu, a1, q);
        float c2 = __shfl_sync(0xffffffffu, a2, q);
        float v0 = c0 * sW1[j]     + c1 * sW1[F1 + j]     + c2 * sW1[2 * F1 + j]     + sb1[j];
        float v1 = c0 * sW1[j + 1] + c1 * sW1[F1 + j + 1] + c2 * sW1[2 * F1 + j + 1] + sb1[j + 1];
        ((__half2*)&h1m[(size_t)(wbase + q) * F1])[lane] =
            __floats2half2_rn(leaky(v0), leaky(v1));
    }
}

// ---------- K2: molecule-per-block: gather(smem) + HMMA + pool + project ----------
#define AGG_PITCH 72   // halfs; ldmatrix conflict-free
// dynamic smem layout (halfs)
#define SH1_HALFS   (NA * F1)                       // 65536 halfs (131072 B)
#define SW2_OFF     SH1_HALFS                       // 64*72 = 4608 halfs
#define SAGG_OFF    (SW2_OFF + F1 * AGG_PITCH)      // 128*72 = 9216 halfs
#define SMEM_MOL_BYTES ((SAGG_OFF + TILE * AGG_PITCH) * 2)   // 158720 B

__global__ void __launch_bounds__(512, 1)
k_mol(const float* __restrict__ W2, const float* __restrict__ b2,
      const float* __restrict__ Wp, const float* __restrict__ bp,
      float* __restrict__ outp) {
    extern __shared__ __half smh[];
    __half* sh1  = smh;
    __half* sW2h = smh + SW2_OFF;
    __half* sagg = smh + SAGG_OFF;
    __shared__ float pool_sm[16][32];
    __shared__ float poolacc[F1];
    __shared__ float gs[F1];

    int b = blockIdx.x;
    int tid = threadIdx.x, wid = tid >> 5, lane = tid & 31;

    // stage W2 as fp16 (padded pitch)
    for (int t = tid; t < F1 * F1; t += 512) {
        int k = t >> 6, j = t & 63;
        sW2h[k * AGG_PITCH + j] = __float2half_rn(W2[t]);
    }
    // load the whole molecule's h1 (128 KB) coalesced
    {
        const float4* src = (const float4*)&g_h1[(size_t)b * NA * F1];
        float4* dst = (float4*)sh1;
#pragma unroll
        for (int i = 0; i < 16; i++) dst[i * 512 + tid] = src[i * 512 + tid];
    }
    if (tid < F1) poolacc[tid] = 0.0f;
    __syncthreads();

    const __half2* sh1v = (const __half2*)sh1;      // row stride 32 half2

    unsigned sagg_b = smem_u32(sagg);
    unsigned sw2_b  = smem_u32(sW2h);
    int m0 = (wid >> 1) * 16;
    int j0 = (wid & 1) * 32;
    int grp = lane >> 3, lr = lane & 7;
    int t4 = lane & 3;

    for (int tile = 0; tile < NTILES; tile++) {
        int base = tile * TILE;

        // ---- Phase A: warp-per-atom gather from smem ----
        for (int a = wid; a < TILE; a += 16) {
            int atom = base + a;
            float ns = g_nself[atom];
            float2 v = __half22float2(sh1v[atom * 32 + lane]);
            float ax = ns * v.x, ay = ns * v.y;
            int r0 = g_rowptr[atom], r1 = g_rowptr[atom + 1];
#pragma unroll 4
            for (int e = r0; e < r1; e++) {
                int s   = g_csrsrc[e];
                float w = g_csrnorm[e];
                float2 rv = __half22float2(sh1v[s * 32 + lane]);  // conflict-free LDS
                ax += w * rv.x;
                ay += w * rv.y;
            }
            ((__half2*)&sagg[a * AGG_PITCH])[lane] = __floats2half2_rn(ax, ay);
        }
        __syncthreads();

        // ---- Phase B: 128x64x64 HMMA; warp tile m16 x n32 ----
        float c[4][4];
#pragma unroll
        for (int q = 0; q < 4; q++)
#pragma unroll
            for (int r = 0; r < 4; r++) c[q][r] = 0.0f;

#pragma unroll
        for (int kc = 0; kc < F1; kc += 16) {
            int arow = m0 + (grp & 1) * 8 + lr;
            int acol = kc + (grp >> 1) * 8;
            unsigned a0, a1, a2, a3;
            ldsm_x4(sagg_b + (arow * AGG_PITCH + acol) * 2, a0, a1, a2, a3);

            int brow = kc + (grp & 1) * 8 + lr;
#pragma unroll
            for (int p = 0; p < 2; p++) {
                int bcol = j0 + p * 16 + (grp >> 1) * 8;
                unsigned b0, b1, b2r, b3;
                ldsm_x4t(sw2_b + (brow * AGG_PITCH + bcol) * 2, b0, b1, b2r, b3);
                mma16816(c[2 * p],     a0, a1, a2, a3, b0,  b1);
                mma16816(c[2 * p + 1], a0, a1, a2, a3, b2r, b3);
            }
        }

        // bias + leaky + pool-reduce over the warp's 16 atom rows
#pragma unroll
        for (int nt = 0; nt < 4; nt++) {
            int jb = j0 + nt * 8 + 2 * t4;
            float bb0 = __ldg(&b2[jb]), bb1 = __ldg(&b2[jb + 1]);
            float s0 = leaky(c[nt][0] + bb0) + leaky(c[nt][2] + bb0);
            float s1 = leaky(c[nt][1] + bb1) + leaky(c[nt][3] + bb1);
#pragma unroll
            for (int o = 4; o < 32; o <<= 1) {
                s0 += __shfl_xor_sync(0xffffffffu, s0, o);
                s1 += __shfl_xor_sync(0xffffffffu, s1, o);
            }
            if (lane < 4) {
                pool_sm[wid][nt * 8 + 2 * t4]     = s0;
                pool_sm[wid][nt * 8 + 2 * t4 + 1] = s1;
            }
        }
        __syncthreads();

        // combine 8 m-tile warps per feature into the molecule accumulator
        if (tid < F1) {
            int nh = tid >> 5, cw = tid & 31;
            float s = 0.0f;
#pragma unroll
            for (int m = 0; m < 8; m++) s += pool_sm[m * 2 + nh][cw];
            poolacc[tid] += s;
        }
        __syncthreads();
    }

    // ---- mean pool + projection + leaky, straight to output ----
    if (tid < F1) gs[tid] = poolacc[tid] * (1.0f / NA);
    __syncthreads();
    if (tid < FP) {
        float v = bp[tid];
#pragma unroll
        for (int k = 0; k < F1; k++) v += gs[k] * Wp[k * FP + tid];
        outp[(size_t)b * FP + tid] = leaky(v);
    }
}

// ---------- launch ----------
extern "C" void kernel_launch(void* const* d_in, const int* in_sizes, int n_in,
                              void* d_out, int out_size) {
    const float* x        = (const float*)d_in[0];
    const unsigned int* e = (const unsigned int*)d_in[1];
    const float* W1       = (const float*)d_in[2];
    const float* b1       = (const float*)d_in[3];
    const float* W2       = (const float*)d_in[4];
    const float* b2       = (const float*)d_in[5];
    const float* Wp       = (const float*)d_in[6];
    const float* bp       = (const float*)d_in[7];
    float* out            = (float*)d_out;

    // idempotent host-side attribute set (capture-safe, no allocation)
    cudaFuncSetAttribute(k_mol, cudaFuncAttributeMaxDynamicSharedMemorySize,
                         SMEM_MOL_BYTES);

    k_setup<<<1, NA>>>(e);
    k_layer1<<<NB, NA>>>(x, W1, b1);
    k_mol<<<NB, 512, SMEM_MOL_BYTES>>>(W2, b2, Wp, bp, out);
}

// round 9
// speedup vs baseline: 3.0483x; 1.1852x over previous
#include <cuda_runtime.h>
#include <cuda_fp16.h>
#include <cstdint>

#define NB 256
#define NA 1024
#define NE 8192
#define F1 64
#define FP 128
#define SLOPE 0.01f
#define TILE 128
#define NTILES (NA / TILE)

// ---------- device scratch (allocation-free: static globals) ----------
__device__ float  g_nself[NA];
__device__ int    g_rowptr[NA + 1];
__device__ int    g_csrsrc[NE];
__device__ float  g_csrnorm[NE];

__device__ __forceinline__ float leaky(float v) {
    return v >= 0.0f ? v : SLOPE * v;
}

__device__ __forceinline__ unsigned smem_u32(const void* p) {
    return (unsigned)__cvta_generic_to_shared(p);
}
__device__ __forceinline__ void ldsm_x4(unsigned addr, unsigned& r0, unsigned& r1,
                                        unsigned& r2, unsigned& r3) {
    asm volatile("ldmatrix.sync.aligned.m8n8.x4.shared.b16 {%0,%1,%2,%3}, [%4];"
                 : "=r"(r0), "=r"(r1), "=r"(r2), "=r"(r3) : "r"(addr));
}
__device__ __forceinline__ void ldsm_x4t(unsigned addr, unsigned& r0, unsigned& r1,
                                         unsigned& r2, unsigned& r3) {
    asm volatile("ldmatrix.sync.aligned.m8n8.x4.trans.shared.b16 {%0,%1,%2,%3}, [%4];"
                 : "=r"(r0), "=r"(r1), "=r"(r2), "=r"(r3) : "r"(addr));
}
__device__ __forceinline__ void mma16816(float* c, unsigned a0, unsigned a1,
                                         unsigned a2, unsigned a3,
                                         unsigned b0, unsigned b1) {
    asm volatile(
        "mma.sync.aligned.m16n8k16.row.col.f32.f16.f16.f32 "
        "{%0,%1,%2,%3}, {%4,%5,%6,%7}, {%8,%9}, {%0,%1,%2,%3};"
        : "+f"(c[0]), "+f"(c[1]), "+f"(c[2]), "+f"(c[3])
        : "r"(a0), "r"(a1), "r"(a2), "r"(a3), "r"(b0), "r"(b1));
}

// ---------- K0: degrees, norms, CSR build (one block, warp-scan) ----------
__global__ void k_setup(const unsigned int* __restrict__ ei_raw) {
    __shared__ int   scnt[NA];
    __shared__ float sdinv[NA];
    __shared__ int   scur[NA];
    __shared__ int   warpsum[32];
    __shared__ int   s_is64;
    int tid = threadIdx.x, lane = tid & 31, wid = tid >> 5;

    if (tid < 32) {   // int64 edge_index has zero high words (values < 1024)
        unsigned m = __ballot_sync(0xffffffffu, ei_raw[2 * tid + 1] != 0u);
        if (tid == 0) s_is64 = (m == 0u);
    }
    scnt[tid] = 0;
    __syncthreads();
    const int is64 = s_is64;

    // in-degree histogram over dst (smem atomics)
    for (int e = tid; e < NE; e += NA) {
        int d = is64 ? (int)ei_raw[2 * (NE + e)] : (int)ei_raw[NE + e];
        atomicAdd(&scnt[d], 1);
    }
    __syncthreads();

    int my = scnt[tid];
    float dinv = rsqrtf((float)(my + 1));   // deg = 1 + in-degree (self loop)
    sdinv[tid]   = dinv;
    g_nself[tid] = dinv * dinv;

    // warp-shfl inclusive scan (2 barriers instead of 20)
    int v = my;
#pragma unroll
    for (int o = 1; o < 32; o <<= 1) {
        int t = __shfl_up_sync(0xffffffffu, v, o);
        if (lane >= o) v += t;
    }
    if (lane == 31) warpsum[wid] = v;
    __syncthreads();
    if (wid == 0) {
        int w = warpsum[lane];
#pragma unroll
        for (int o = 1; o < 32; o <<= 1) {
            int t = __shfl_up_sync(0xffffffffu, w, o);
            if (lane >= o) w += t;
        }
        warpsum[lane] = w;
    }
    __syncthreads();
    int excl = v + (wid > 0 ? warpsum[wid - 1] : 0) - my;
    scur[tid]     = excl;
    g_rowptr[tid] = excl;
    if (tid == 0) g_rowptr[NA] = NE;
    __syncthreads();

    // scatter edges into CSR rows keyed by dst
    for (int e = tid; e < NE; e += NA) {
        int s = is64 ? (int)ei_raw[2 * e]        : (int)ei_raw[e];
        int d = is64 ? (int)ei_raw[2 * (NE + e)] : (int)ei_raw[NE + e];
        int pos = atomicAdd(&scur[d], 1);
        g_csrsrc[pos]  = s;
        g_csrnorm[pos] = sdinv[s] * sdinv[d];
    }
}

// ---------- K1: whole network per molecule in one block ----------
#define AGG_PITCH 72   // halfs; ldmatrix conflict-free
#define SW2_OFF   (NA * F1)                       // after sh1 (65536 halfs)
#define SAGG_OFF  (SW2_OFF + F1 * AGG_PITCH)
#define SMEM_MOL_BYTES ((SAGG_OFF + TILE * AGG_PITCH) * 2)   // 158720 B

__global__ void __launch_bounds__(512, 1)
k_mol(const float* __restrict__ x,
      const float* __restrict__ W1, const float* __restrict__ b1,
      const float* __restrict__ W2, const float* __restrict__ b2,
      const float* __restrict__ Wp, const float* __restrict__ bp,
      float* __restrict__ outp) {
    extern __shared__ __half smh[];
    __half* sh1  = smh;                           // [1024][64] fp16
    __half* sW2h = smh + SW2_OFF;
    __half* sagg = smh + SAGG_OFF;
    float*  sx   = (float*)(smh + SAGG_OFF);      // alias: dead before sagg used
    __shared__ float sW1[3 * F1];
    __shared__ float sb1[F1];
    __shared__ float pool_sm[16][32];
    __shared__ float gs[F1];

    int b = blockIdx.x;
    int tid = threadIdx.x, wid = tid >> 5, lane = tid & 31;
    int wbase32 = (tid & ~31) ;                   // warp's base thread id

    // stage x (12 KB), W1, b1, W2(fp16)
    const float* xb = x + (size_t)b * (NA * 3);
    for (int t = tid; t < NA * 3; t += 512) sx[t] = xb[t];
    if (tid < 3 * F1) sW1[tid] = W1[tid];
    if (tid < F1)     sb1[tid] = b1[tid];
    for (int t = tid; t < F1 * F1; t += 512) {
        int k = t >> 6, j = t & 63;
        sW2h[k * AGG_PITCH + j] = __float2half_rn(W2[t]);
    }
    __syncthreads();

    // ---- Layer 1: agg 3 raw feats over edges, h1 = leaky(agg@W1+b1) -> sh1 ----
    int j2 = 2 * lane;
#pragma unroll
    for (int g = 0; g < 2; g++) {
        int atom = g * 512 + tid;
        float ns = g_nself[atom];
        float a0 = ns * sx[atom * 3 + 0];
        float a1 = ns * sx[atom * 3 + 1];
        float a2 = ns * sx[atom * 3 + 2];
        int r0 = g_rowptr[atom], r1 = g_rowptr[atom + 1];
#pragma unroll 4
        for (int e = r0; e < r1; e++) {
            int s = g_csrsrc[e];
            float w = g_csrnorm[e];
            a0 += w * sx[s * 3 + 0];
            a1 += w * sx[s * 3 + 1];
            a2 += w * sx[s * 3 + 2];
        }
        // in-warp transpose: lane l writes features 2l,2l+1 of each atom row
        int rowbase = g * 512 + wbase32;
#pragma unroll 4
        for (int q = 0; q < 32; q++) {
            float c0 = __shfl_sync(0xffffffffu, a0, q);
            float c1 = __shfl_sync(0xffffffffu, a1, q);
            float c2 = __shfl_sync(0xffffffffu, a2, q);
            float v0 = c0 * sW1[j2]     + c1 * sW1[F1 + j2]     + c2 * sW1[2 * F1 + j2]     + sb1[j2];
            float v1 = c0 * sW1[j2 + 1] + c1 * sW1[F1 + j2 + 1] + c2 * sW1[2 * F1 + j2 + 1] + sb1[j2 + 1];
            ((__half2*)&sh1[(size_t)(rowbase + q) * F1])[lane] =
                __floats2half2_rn(leaky(v0), leaky(v1));
        }
    }
    __syncthreads();   // sh1 complete; sx dead (sagg may now be overwritten)

    // ---- Layer 2 tiles: gather(smem) + HMMA + pool (register accumulate) ----
    const __half2* sh1v = (const __half2*)sh1;    // row stride 32 half2
    unsigned sagg_b = smem_u32(sagg);
    unsigned sw2_b  = smem_u32(sW2h);
    int m0 = (wid >> 1) * 16;
    int j0 = (wid & 1) * 32;
    int grp = lane >> 3, lr = lane & 7;
    int t4 = lane & 3;

    float pacc[4][2];
#pragma unroll
    for (int nt = 0; nt < 4; nt++) pacc[nt][0] = pacc[nt][1] = 0.0f;

    for (int tile = 0; tile < NTILES; tile++) {
        int base = tile * TILE;

        // Phase A: warp-per-atom gather from smem
        for (int a = wid; a < TILE; a += 16) {
            int atom = base + a;
            float ns = g_nself[atom];
            float2 v = __half22float2(sh1v[atom * 32 + lane]);
            float ax = ns * v.x, ay = ns * v.y;
            int r0 = g_rowptr[atom], r1 = g_rowptr[atom + 1];
#pragma unroll 4
            for (int e = r0; e < r1; e++) {
                int s   = g_csrsrc[e];
                float w = g_csrnorm[e];
                float2 rv = __half22float2(sh1v[s * 32 + lane]);  // conflict-free LDS
                ax += w * rv.x;
                ay += w * rv.y;
            }
            ((__half2*)&sagg[a * AGG_PITCH])[lane] = __floats2half2_rn(ax, ay);
        }
        __syncthreads();

        // Phase B: 128x64x64 HMMA; warp tile m16 x n32
        float c[4][4];
#pragma unroll
        for (int q = 0; q < 4; q++)
#pragma unroll
            for (int r = 0; r < 4; r++) c[q][r] = 0.0f;

#pragma unroll
        for (int kc = 0; kc < F1; kc += 16) {
            int arow = m0 + (grp & 1) * 8 + lr;
            int acol = kc + (grp >> 1) * 8;
            unsigned a0, a1, a2, a3;
            ldsm_x4(sagg_b + (arow * AGG_PITCH + acol) * 2, a0, a1, a2, a3);

            int brow = kc + (grp & 1) * 8 + lr;
#pragma unroll
            for (int p = 0; p < 2; p++) {
                int bcol = j0 + p * 16 + (grp >> 1) * 8;
                unsigned b0, b1, b2r, b3;
                ldsm_x4t(sw2_b + (brow * AGG_PITCH + bcol) * 2, b0, b1, b2r, b3);
                mma16816(c[2 * p],     a0, a1, a2, a3, b0,  b1);
                mma16816(c[2 * p + 1], a0, a1, a2, a3, b2r, b3);
            }
        }

        // bias + leaky + shfl pool-reduce; accumulate in registers across tiles
#pragma unroll
        for (int nt = 0; nt < 4; nt++) {
            int jb = j0 + nt * 8 + 2 * t4;
            float bb0 = __ldg(&b2[jb]), bb1 = __ldg(&b2[jb + 1]);
            float s0 = leaky(c[nt][0] + bb0) + leaky(c[nt][2] + bb0);
            float s1 = leaky(c[nt][1] + bb1) + leaky(c[nt][3] + bb1);
#pragma unroll
            for (int o = 4; o < 32; o <<= 1) {
                s0 += __shfl_xor_sync(0xffffffffu, s0, o);
                s1 += __shfl_xor_sync(0xffffffffu, s1, o);
            }
            pacc[nt][0] += s0;
            pacc[nt][1] += s1;
        }
        __syncthreads();   // sagg consumed; safe to overwrite next tile
    }

    // ---- write pool partials once, combine, mean, project ----
    if (lane < 4) {
#pragma unroll
        for (int nt = 0; nt < 4; nt++) {
            pool_sm[wid][nt * 8 + 2 * t4]     = pacc[nt][0];
            pool_sm[wid][nt * 8 + 2 * t4 + 1] = pacc[nt][1];
        }
    }
    __syncthreads();

    if (tid < F1) {
        int nh = tid >> 5, cw = tid & 31;
        float s = 0.0f;
#pragma unroll
        for (int m = 0; m < 8; m++) s += pool_sm[m * 2 + nh][cw];
        gs[tid] = s * (1.0f / NA);
    }
    __syncthreads();

    if (tid < FP) {
        float v = bp[tid];
#pragma unroll
        for (int k = 0; k < F1; k++) v += gs[k] * Wp[k * FP + tid];
        outp[(size_t)b * FP + tid] = leaky(v);
    }
}

// ---------- launch ----------
extern "C" void kernel_launch(void* const* d_in, const int* in_sizes, int n_in,
                              void* d_out, int out_size) {
    const float* x        = (const float*)d_in[0];
    const unsigned int* e = (const unsigned int*)d_in[1];
    const float* W1       = (const float*)d_in[2];
    const float* b1       = (const float*)d_in[3];
    const float* W2       = (const float*)d_in[4];
    const float* b2       = (const float*)d_in[5];
    const float* Wp       = (const float*)d_in[6];
    const float* bp       = (const float*)d_in[7];
    float* out            = (float*)d_out;

    // idempotent host-side attribute set (capture-safe, no allocation)
    cudaFuncSetAttribute(k_mol, cudaFuncAttributeMaxDynamicSharedMemorySize,
                         SMEM_MOL_BYTES);

    k_setup<<<1, NA>>>(e);
    k_mol<<<NB, 512, SMEM_MOL_BYTES>>>(x, W1, b1, W2, b2, Wp, bp, out);
}

// round 10
// speedup vs baseline: 3.6998x; 1.2137x over previous
#include <cuda_runtime.h>
#include <cuda_fp16.h>
#include <cstdint>

#define NB 256
#define NA 1024
#define NE 8192
#define F1 64
#define FP 128
#define SLOPE 0.01f
#define TILE 256
#define NTILES (NA / TILE)

// ---------- device scratch (allocation-free: static globals) ----------
__device__ float  g_nself[NA];
__device__ int    g_rowptr[NA + 1];
__device__ int2   g_csredge[NE];     // .x = src, .y = bitcast(norm)  (one LDG.64/edge)

__device__ __forceinline__ float leaky(float v) {
    return v >= 0.0f ? v : SLOPE * v;
}

__device__ __forceinline__ unsigned smem_u32(const void* p) {
    return (unsigned)__cvta_generic_to_shared(p);
}
__device__ __forceinline__ void ldsm_x4(unsigned addr, unsigned& r0, unsigned& r1,
                                        unsigned& r2, unsigned& r3) {
    asm volatile("ldmatrix.sync.aligned.m8n8.x4.shared.b16 {%0,%1,%2,%3}, [%4];"
                 : "=r"(r0), "=r"(r1), "=r"(r2), "=r"(r3) : "r"(addr));
}
__device__ __forceinline__ void ldsm_x4t(unsigned addr, unsigned& r0, unsigned& r1,
                                         unsigned& r2, unsigned& r3) {
    asm volatile("ldmatrix.sync.aligned.m8n8.x4.trans.shared.b16 {%0,%1,%2,%3}, [%4];"
                 : "=r"(r0), "=r"(r1), "=r"(r2), "=r"(r3) : "r"(addr));
}
__device__ __forceinline__ void mma16816(float* c, unsigned a0, unsigned a1,
                                         unsigned a2, unsigned a3,
                                         unsigned b0, unsigned b1) {
    asm volatile(
        "mma.sync.aligned.m16n8k16.row.col.f32.f16.f16.f32 "
        "{%0,%1,%2,%3}, {%4,%5,%6,%7}, {%8,%9}, {%0,%1,%2,%3};"
        : "+f"(c[0]), "+f"(c[1]), "+f"(c[2]), "+f"(c[3])
        : "r"(a0), "r"(a1), "r"(a2), "r"(a3), "r"(b0), "r"(b1));
}

// ---------- K0: degrees, norms, CSR build (one block, warp-scan) ----------
__global__ void k_setup(const unsigned int* __restrict__ ei_raw) {
    __shared__ int   scnt[NA];
    __shared__ float sdinv[NA];
    __shared__ int   scur[NA];
    __shared__ int   warpsum[32];
    __shared__ int   s_is64;
    int tid = threadIdx.x, lane = tid & 31, wid = tid >> 5;

    if (tid < 32) {   // int64 edge_index has zero high words (values < 1024)
        unsigned m = __ballot_sync(0xffffffffu, ei_raw[2 * tid + 1] != 0u);
        if (tid == 0) s_is64 = (m == 0u);
    }
    scnt[tid] = 0;
    __syncthreads();
    const int is64 = s_is64;

    for (int e = tid; e < NE; e += NA) {
        int d = is64 ? (int)ei_raw[2 * (NE + e)] : (int)ei_raw[NE + e];
        atomicAdd(&scnt[d], 1);
    }
    __syncthreads();

    int my = scnt[tid];
    float dinv = rsqrtf((float)(my + 1));   // deg = 1 + in-degree (self loop)
    sdinv[tid]   = dinv;
    g_nself[tid] = dinv * dinv;

    // warp-shfl inclusive scan
    int v = my;
#pragma unroll
    for (int o = 1; o < 32; o <<= 1) {
        int t = __shfl_up_sync(0xffffffffu, v, o);
        if (lane >= o) v += t;
    }
    if (lane == 31) warpsum[wid] = v;
    __syncthreads();
    if (wid == 0) {
        int w = warpsum[lane];
#pragma unroll
        for (int o = 1; o < 32; o <<= 1) {
            int t = __shfl_up_sync(0xffffffffu, w, o);
            if (lane >= o) w += t;
        }
        warpsum[lane] = w;
    }
    __syncthreads();
    int excl = v + (wid > 0 ? warpsum[wid - 1] : 0) - my;
    scur[tid]     = excl;
    g_rowptr[tid] = excl;
    if (tid == 0) g_rowptr[NA] = NE;
    __syncthreads();

    // scatter edges into CSR rows keyed by dst (packed src+norm)
    for (int e = tid; e < NE; e += NA) {
        int s = is64 ? (int)ei_raw[2 * e]        : (int)ei_raw[e];
        int d = is64 ? (int)ei_raw[2 * (NE + e)] : (int)ei_raw[NE + e];
        int pos = atomicAdd(&scur[d], 1);
        g_csredge[pos] = make_int2(s, __float_as_int(sdinv[s] * sdinv[d]));
    }
}

// ---------- K1: whole network per molecule, 1024 threads ----------
#define AGG_PITCH 72   // halfs; ldmatrix conflict-free
#define SW2_OFF   (NA * F1)                       // after sh1 (65536 halfs)
#define SAGG_OFF  (SW2_OFF + F1 * AGG_PITCH)
#define SMEM_MOL_BYTES ((SAGG_OFF + TILE * AGG_PITCH) * 2)   // 177152 B

__global__ void __launch_bounds__(1024, 1)
k_mol(const float* __restrict__ x,
      const float* __restrict__ W1, const float* __restrict__ b1,
      const float* __restrict__ W2, const float* __restrict__ b2,
      const float* __restrict__ Wp, const float* __restrict__ bp,
      float* __restrict__ outp) {
    extern __shared__ __half smh[];
    __half* sh1  = smh;                           // [1024][64] fp16
    __half* sW2h = smh + SW2_OFF;
    __half* sagg = smh + SAGG_OFF;
    float*  sx   = (float*)(smh + SAGG_OFF);      // alias: dead before sagg used
    __shared__ float sW1[3 * F1];
    __shared__ float sb1[F1];
    __shared__ float pool_sm[32][32];
    __shared__ float gs[F1];

    int b = blockIdx.x;
    int tid = threadIdx.x, wid = tid >> 5, lane = tid & 31;

    // stage x (12 KB), W1, b1, W2(fp16)
    const float* xb = x + (size_t)b * (NA * 3);
    for (int t = tid; t < NA * 3; t += 1024) sx[t] = xb[t];
    if (tid < 3 * F1) sW1[tid] = W1[tid];
    if (tid < F1)     sb1[tid] = b1[tid];
    for (int t = tid; t < F1 * F1; t += 1024) {
        int k = t >> 6, j = t & 63;
        sW2h[k * AGG_PITCH + j] = __float2half_rn(W2[t]);
    }
    __syncthreads();

    // ---- Layer 1: thread = atom; h1 = leaky((A_hat@x)@W1 + b1) -> sh1 ----
    {
        int atom = tid;
        float ns = g_nself[atom];
        float a0 = ns * sx[atom * 3 + 0];
        float a1 = ns * sx[atom * 3 + 1];
        float a2 = ns * sx[atom * 3 + 2];
        int r0 = g_rowptr[atom], r1 = g_rowptr[atom + 1];
#pragma unroll 4
        for (int e = r0; e < r1; e++) {
            int2 ed = g_csredge[e];               // one LDG.64
            float w = __int_as_float(ed.y);
            a0 += w * sx[ed.x * 3 + 0];
            a1 += w * sx[ed.x * 3 + 1];
            a2 += w * sx[ed.x * 3 + 2];
        }
        // in-warp transpose: lane l writes features 2l,2l+1 of each atom row
        int j2 = 2 * lane;
        int rowbase = tid & ~31;
#pragma unroll 4
        for (int q = 0; q < 32; q++) {
            float c0 = __shfl_sync(0xffffffffu, a0, q);
            float c1 = __shfl_sync(0xffffffffu, a1, q);
            float c2 = __shfl_sync(0xffffffffu, a2, q);
            float v0 = c0 * sW1[j2]     + c1 * sW1[F1 + j2]     + c2 * sW1[2 * F1 + j2]     + sb1[j2];
            float v1 = c0 * sW1[j2 + 1] + c1 * sW1[F1 + j2 + 1] + c2 * sW1[2 * F1 + j2 + 1] + sb1[j2 + 1];
            ((__half2*)&sh1[(size_t)(rowbase + q) * F1])[lane] =
                __floats2half2_rn(leaky(v0), leaky(v1));
        }
    }
    __syncthreads();   // sh1 complete; sx dead (sagg may now be overwritten)

    // ---- Layer 2 tiles: gather(smem) + HMMA + pool (register accumulate) ----
    const __half2* sh1v = (const __half2*)sh1;    // row stride 32 half2
    unsigned sagg_b = smem_u32(sagg);
    unsigned sw2_b  = smem_u32(sW2h);
    int m0 = (wid >> 1) * 16;                     // 16 m-tiles
    int j0 = (wid & 1) * 32;                      // 2 n-halves
    int grp = lane >> 3, lr = lane & 7;
    int t4 = lane & 3;

    float pacc[4][2];
#pragma unroll
    for (int nt = 0; nt < 4; nt++) pacc[nt][0] = pacc[nt][1] = 0.0f;

    for (int tile = 0; tile < NTILES; tile++) {
        int base = tile * TILE;

        // Phase A: warp-per-atom gather from smem (8 atoms/warp)
        for (int a = wid; a < TILE; a += 32) {
            int atom = base + a;
            float ns = g_nself[atom];
            float2 v = __half22float2(sh1v[atom * 32 + lane]);
            float ax = ns * v.x, ay = ns * v.y;
            int r0 = g_rowptr[atom], r1 = g_rowptr[atom + 1];
#pragma unroll 4
            for (int e = r0; e < r1; e++) {
                int2 ed = g_csredge[e];           // one LDG.64
                float w = __int_as_float(ed.y);
                float2 rv = __half22float2(sh1v[ed.x * 32 + lane]);  // conflict-free LDS
                ax += w * rv.x;
                ay += w * rv.y;
            }
            ((__half2*)&sagg[a * AGG_PITCH])[lane] = __floats2half2_rn(ax, ay);
        }
        __syncthreads();

        // Phase B: 256x64x64 HMMA; warp tile m16 x n32
        float c[4][4];
#pragma unroll
        for (int q = 0; q < 4; q++)
#pragma unroll
            for (int r = 0; r < 4; r++) c[q][r] = 0.0f;

#pragma unroll
        for (int kc = 0; kc < F1; kc += 16) {
            int arow = m0 + (grp & 1) * 8 + lr;
            int acol = kc + (grp >> 1) * 8;
            unsigned a0, a1, a2, a3;
            ldsm_x4(sagg_b + (arow * AGG_PITCH + acol) * 2, a0, a1, a2, a3);

            int brow = kc + (grp & 1) * 8 + lr;
#pragma unroll
            for (int p = 0; p < 2; p++) {
                int bcol = j0 + p * 16 + (grp >> 1) * 8;
                unsigned b0, b1, b2r, b3;
                ldsm_x4t(sw2_b + (brow * AGG_PITCH + bcol) * 2, b0, b1, b2r, b3);
                mma16816(c[2 * p],     a0, a1, a2, a3, b0,  b1);
                mma16816(c[2 * p + 1], a0, a1, a2, a3, b2r, b3);
            }
        }

        // bias + leaky + shfl pool-reduce; accumulate in registers across tiles
#pragma unroll
        for (int nt = 0; nt < 4; nt++) {
            int jb = j0 + nt * 8 + 2 * t4;
            float bb0 = __ldg(&b2[jb]), bb1 = __ldg(&b2[jb + 1]);
            float s0 = leaky(c[nt][0] + bb0) + leaky(c[nt][2] + bb0);
            float s1 = leaky(c[nt][1] + bb1) + leaky(c[nt][3] + bb1);
#pragma unroll
            for (int o = 4; o < 32; o <<= 1) {
                s0 += __shfl_xor_sync(0xffffffffu, s0, o);
                s1 += __shfl_xor_sync(0xffffffffu, s1, o);
            }
            pacc[nt][0] += s0;
            pacc[nt][1] += s1;
        }
        __syncthreads();   // sagg consumed; safe to overwrite next tile
    }

    // ---- write pool partials once, combine, mean, project ----
    if (lane < 4) {
#pragma unroll
        for (int nt = 0; nt < 4; nt++) {
            pool_sm[wid][nt * 8 + 2 * t4]     = pacc[nt][0];
            pool_sm[wid][nt * 8 + 2 * t4 + 1] = pacc[nt][1];
        }
    }
    __syncthreads();

    if (tid < F1) {
        int nh = tid >> 5, cw = tid & 31;       // n-half, column within half
        float s = 0.0f;
#pragma unroll
        for (int m = 0; m < 16; m++) s += pool_sm[m * 2 + nh][cw];
        gs[tid] = s * (1.0f / NA);
    }
    __syncthreads();

    if (tid < FP) {
        float v = bp[tid];
#pragma unroll
        for (int k = 0; k < F1; k++) v += gs[k] * Wp[k * FP + tid];
        outp[(size_t)b * FP + tid] = leaky(v);
    }
}

// ---------- launch ----------
extern "C" void kernel_launch(void* const* d_in, const int* in_sizes, int n_in,
                              void* d_out, int out_size) {
    const float* x        = (const float*)d_in[0];
    const unsigned int* e = (const unsigned int*)d_in[1];
    const float* W1       = (const float*)d_in[2];
    const float* b1       = (const float*)d_in[3];
    const float* W2       = (const float*)d_in[4];
    const float* b2       = (const float*)d_in[5];
    const float* Wp       = (const float*)d_in[6];
    const float* bp       = (const float*)d_in[7];
    float* out            = (float*)d_out;

    // idempotent host-side attribute set (capture-safe, no allocation)
    cudaFuncSetAttribute(k_mol, cudaFuncAttributeMaxDynamicSharedMemorySize,
                         SMEM_MOL_BYTES);

    k_setup<<<1, NA>>>(e);
    k_mol<<<NB, 1024, SMEM_MOL_BYTES>>>(x, W1, b1, W2, b2, Wp, bp, out);
}

// round 12
// speedup vs baseline: 4.1456x; 1.1205x over previous
#include <cuda_runtime.h>
#include <cuda_fp16.h>
#include <cstdint>

#define NB 256
#define NA 1024
#define NE 8192
#define F1 64
#define FP 128
#define SLOPE 0.01f
#define TILE 256
#define NTILES (NA / TILE)

// ---------- device scratch (allocation-free: static globals) ----------
__device__ float g_nself[NA];
__device__ int   g_rowptr[NA + 1];
__device__ int   g_edgepack[NE];   // (norm_fp16_bits << 16) | (src*4)

__device__ __forceinline__ float leaky(float v) {
    return v >= 0.0f ? v : SLOPE * v;
}

__device__ __forceinline__ __half2 u32_as_half2(unsigned u) {
    __half2 h;
    *(unsigned*)&h = u;
    return h;
}

__device__ __forceinline__ unsigned smem_u32(const void* p) {
    return (unsigned)__cvta_generic_to_shared(p);
}
__device__ __forceinline__ void ldsm_x4(unsigned addr, unsigned& r0, unsigned& r1,
                                        unsigned& r2, unsigned& r3) {
    asm volatile("ldmatrix.sync.aligned.m8n8.x4.shared.b16 {%0,%1,%2,%3}, [%4];"
                 : "=r"(r0), "=r"(r1), "=r"(r2), "=r"(r3) : "r"(addr));
}
__device__ __forceinline__ void ldsm_x4t(unsigned addr, unsigned& r0, unsigned& r1,
                                         unsigned& r2, unsigned& r3) {
    asm volatile("ldmatrix.sync.aligned.m8n8.x4.trans.shared.b16 {%0,%1,%2,%3}, [%4];"
                 : "=r"(r0), "=r"(r1), "=r"(r2), "=r"(r3) : "r"(addr));
}
__device__ __forceinline__ void mma16816(float* c, unsigned a0, unsigned a1,
                                         unsigned a2, unsigned a3,
                                         unsigned b0, unsigned b1) {
    asm volatile(
        "mma.sync.aligned.m16n8k16.row.col.f32.f16.f16.f32 "
        "{%0,%1,%2,%3}, {%4,%5,%6,%7}, {%8,%9}, {%0,%1,%2,%3};"
        : "+f"(c[0]), "+f"(c[1]), "+f"(c[2]), "+f"(c[3])
        : "r"(a0), "r"(a1), "r"(a2), "r"(a3), "r"(b0), "r"(b1));
}

// ---------- K0: degrees, norms, packed CSR build (one block, warp-scan) ----------
__global__ void k_setup(const unsigned int* __restrict__ ei_raw) {
    __shared__ int   scnt[NA];
    __shared__ float sdinv[NA];
    __shared__ int   scur[NA];
    __shared__ int   warpsum[32];
    __shared__ int   s_is64;
    int tid = threadIdx.x, lane = tid & 31, wid = tid >> 5;

    if (tid < 32) {   // int64 edge_index has zero high words (values < 1024)
        unsigned m = __ballot_sync(0xffffffffu, ei_raw[2 * tid + 1] != 0u);
        if (tid == 0) s_is64 = (m == 0u);
    }
    scnt[tid] = 0;
    __syncthreads();
    const int is64 = s_is64;

    for (int e = tid; e < NE; e += NA) {
        int d = is64 ? (int)ei_raw[2 * (NE + e)] : (int)ei_raw[NE + e];
        atomicAdd(&scnt[d], 1);
    }
    __syncthreads();

    int my = scnt[tid];
    float dinv = rsqrtf((float)(my + 1));   // deg = 1 + in-degree (self loop)
    sdinv[tid]   = dinv;
    g_nself[tid] = dinv * dinv;

    // warp-shfl inclusive scan
    int v = my;
#pragma unroll
    for (int o = 1; o < 32; o <<= 1) {
        int t = __shfl_up_sync(0xffffffffu, v, o);
        if (lane >= o) v += t;
    }
    if (lane == 31) warpsum[wid] = v;
    __syncthreads();
    if (wid == 0) {
        int w = warpsum[lane];
#pragma unroll
        for (int o = 1; o < 32; o <<= 1) {
            int t = __shfl_up_sync(0xffffffffu, w, o);
            if (lane >= o) w += t;
        }
        warpsum[lane] = w;
    }
    __syncthreads();
    int excl = v + (wid > 0 ? warpsum[wid - 1] : 0) - my;
    scur[tid]     = excl;
    g_rowptr[tid] = excl;
    if (tid == 0) g_rowptr[NA] = NE;
    __syncthreads();

    // scatter edges: pack norm (fp16) + src*4 into one int
    for (int e = tid; e < NE; e += NA) {
        int s = is64 ? (int)ei_raw[2 * e]        : (int)ei_raw[e];
        int d = is64 ? (int)ei_raw[2 * (NE + e)] : (int)ei_raw[NE + e];
        int pos = atomicAdd(&scur[d], 1);
        unsigned nh = __half_as_ushort(__float2half_rn(sdinv[s] * sdinv[d]));
        g_edgepack[pos] = (int)((nh << 16) | (unsigned)(s * 4));
    }
}

// ---------- K1: whole network per molecule, 1024 threads ----------
#define AGG_PITCH 72   // halfs; ldmatrix conflict-free
#define SW2_OFF   (NA * F1)                        // 65536 halfs
#define SAGG_OFF  (SW2_OFF + F1 * AGG_PITCH)       // + 4608
#define SEDGE_OFF (SAGG_OFF + TILE * AGG_PITCH)    // + 18432 (halfs)
#define SMEM_MOL_BYTES ((SEDGE_OFF + 2 * NE) * 2)  // + 32768 B edges = 209920 B

__global__ void __launch_bounds__(1024, 1)
k_mol(const float* __restrict__ x,
      const float* __restrict__ W1, const float* __restrict__ b1,
      const float* __restrict__ W2, const float* __restrict__ b2,
      const float* __restrict__ Wp, const float* __restrict__ bp,
      float* __restrict__ outp) {
    extern __shared__ __half smh[];
    __half* sh1  = smh;                            // [1024][64] fp16
    __half* sW2h = smh + SW2_OFF;
    __half* sagg = smh + SAGG_OFF;
    int*    sedge = (int*)(smh + SEDGE_OFF);       // 8192 packed edges
    float*  sx   = (float*)(smh + SAGG_OFF);       // alias sagg: dead before sagg used
    __shared__ float sW1[3 * F1];
    __shared__ float sb1[F1];
    __shared__ float pool_sm[32][32];
    __shared__ float gs[F1];

    int b = blockIdx.x;
    int tid = threadIdx.x, wid = tid >> 5, lane = tid & 31;

    // stage x (12 KB), edges (32 KB), W1, b1, W2(fp16)
    const float* xb = x + (size_t)b * (NA * 3);
    for (int t = tid; t < NA * 3; t += 1024) sx[t] = xb[t];
#pragma unroll
    for (int t = 0; t < NE / 1024; t++) sedge[t * 1024 + tid] = g_edgepack[t * 1024 + tid];
    if (tid < 3 * F1) sW1[tid] = W1[tid];
    if (tid < F1)     sb1[tid] = b1[tid];
    for (int t = tid; t < F1 * F1; t += 1024) {
        int k = t >> 6, j = t & 63;
        sW2h[k * AGG_PITCH + j] = __float2half_rn(W2[t]);
    }
    __syncthreads();

    // ---- Layer 1: thread = atom; h1 = leaky((A_hat@x)@W1 + b1) -> sh1 ----
    {
        int atom = tid;
        float ns = g_nself[atom];
        float a0 = ns * sx[atom * 3 + 0];
        float a1 = ns * sx[atom * 3 + 1];
        float a2 = ns * sx[atom * 3 + 2];
        int r0 = g_rowptr[atom], r1 = g_rowptr[atom + 1];
#pragma unroll 4
        for (int e = r0; e < r1; e++) {
            int pe = sedge[e];
            float w = __half2float(__ushort_as_half((unsigned short)((unsigned)pe >> 16)));
            int s3 = ((pe & 0xFFFF) >> 2) * 3;
            a0 += w * sx[s3 + 0];
            a1 += w * sx[s3 + 1];
            a2 += w * sx[s3 + 2];
        }
        // in-warp transpose: lane l writes features 2l,2l+1 of each atom row
        int j2 = 2 * lane;
        int rowbase = tid & ~31;
#pragma unroll 4
        for (int q = 0; q < 32; q++) {
            float c0 = __shfl_sync(0xffffffffu, a0, q);
            float c1 = __shfl_sync(0xffffffffu, a1, q);
            float c2 = __shfl_sync(0xffffffffu, a2, q);
            float v0 = c0 * sW1[j2]     + c1 * sW1[F1 + j2]     + c2 * sW1[2 * F1 + j2]     + sb1[j2];
            float v1 = c0 * sW1[j2 + 1] + c1 * sW1[F1 + j2 + 1] + c2 * sW1[2 * F1 + j2 + 1] + sb1[j2 + 1];
            ((__half2*)&sh1[(size_t)(rowbase + q) * F1])[lane] =
                __floats2half2_rn(leaky(v0), leaky(v1));
        }
    }
    __syncthreads();   // sh1 complete; sx dead (sagg may now be overwritten)

    // ---- Layer 2 tiles: fp16 gather(smem) + HMMA + pool ----
    const char* sh1c = (const char*)sh1 + lane * 4;   // lane's half2 within any row
    unsigned sagg_b = smem_u32(sagg);
    unsigned sw2_b  = smem_u32(sW2h);
    int m0 = (wid >> 1) * 16;
    int j0 = (wid & 1) * 32;
    int grp = lane >> 3, lr = lane & 7;
    int t4 = lane & 3;

    float pacc[4][2];
#pragma unroll
    for (int nt = 0; nt < 4; nt++) pacc[nt][0] = pacc[nt][1] = 0.0f;

    for (int tile = 0; tile < NTILES; tile++) {
        int base = tile * TILE;

        // Phase A: warp-per-atom gather, half2 HFMA2 accumulation
        for (int a = wid; a < TILE; a += 32) {
            int atom = base + a;
            __half2 ns2 = __float2half2_rn(g_nself[atom]);
            __half2 acc = __hmul2(ns2, *(const __half2*)(sh1c + atom * 128));
            int r0 = g_rowptr[atom], r1 = g_rowptr[atom + 1];
#pragma unroll 4
            for (int e = r0; e < r1; e++) {
                int pe = sedge[e];                                   // LDS broadcast
                __half2 w2 = u32_as_half2(__byte_perm(pe, pe, 0x3232));
                __half2 rv = *(const __half2*)(sh1c + ((pe & 0xFFFF) << 5));
                acc = __hfma2(w2, rv, acc);
            }
            ((__half2*)&sagg[a * AGG_PITCH])[lane] = acc;
        }
        __syncthreads();

        // Phase B: 256x64x64 HMMA; warp tile m16 x n32
        float c[4][4];
#pragma unroll
        for (int q = 0; q < 4; q++)
#pragma unroll
            for (int r = 0; r < 4; r++) c[q][r] = 0.0f;

#pragma unroll
        for (int kc = 0; kc < F1; kc += 16) {
            int arow = m0 + (grp & 1) * 8 + lr;
            int acol = kc + (grp >> 1) * 8;
            unsigned a0, a1, a2, a3;
            ldsm_x4(sagg_b + (arow * AGG_PITCH + acol) * 2, a0, a1, a2, a3);

            int brow = kc + (grp & 1) * 8 + lr;
#pragma unroll
            for (int p = 0; p < 2; p++) {
                int bcol = j0 + p * 16 + (grp >> 1) * 8;
                unsigned b0, b1, b2r, b3;
                ldsm_x4t(sw2_b + (brow * AGG_PITCH + bcol) * 2, b0, b1, b2r, b3);
                mma16816(c[2 * p],     a0, a1, a2, a3, b0,  b1);
                mma16816(c[2 * p + 1], a0, a1, a2, a3, b2r, b3);
            }
        }

        // bias + leaky + shfl pool-reduce; accumulate in registers across tiles
#pragma unroll
        for (int nt = 0; nt < 4; nt++) {
            int jb = j0 + nt * 8 + 2 * t4;
            float bb0 = __ldg(&b2[jb]), bb1 = __ldg(&b2[jb + 1]);
            float s0 = leaky(c[nt][0] + bb0) + leaky(c[nt][2] + bb0);
            float s1 = leaky(c[nt][1] + bb1) + leaky(c[nt][3] + bb1);
#pragma unroll
            for (int o = 4; o < 32; o <<= 1) {
                s0 += __shfl_xor_sync(0xffffffffu, s0, o);
                s1 += __shfl_xor_sync(0xffffffffu, s1, o);
            }
            pacc[nt][0] += s0;
            pacc[nt][1] += s1;
        }
        __syncthreads();   // sagg consumed; safe to overwrite next tile
    }

    // ---- write pool partials once, combine, mean, project ----
    if (lane < 4) {
#pragma unroll
        for (int nt = 0; nt < 4; nt++) {
            pool_sm[wid][nt * 8 + 2 * t4]     = pacc[nt][0];
            pool_sm[wid][nt * 8 + 2 * t4 + 1] = pacc[nt][1];
        }
    }
    __syncthreads();

    if (tid < F1) {
        int nh = tid >> 5, cw = tid & 31;
        float s = 0.0f;
#pragma unroll
        for (int m = 0; m < 16; m++) s += pool_sm[m * 2 + nh][cw];
        gs[tid] = s * (1.0f / NA);
    }
    __syncthreads();

    if (tid < FP) {
        float v = bp[tid];
#pragma unroll
        for (int k = 0; k < F1; k++) v += gs[k] * Wp[k * FP + tid];
        outp[(size_t)b * FP + tid] = leaky(v);
    }
}

// ---------- launch ----------
extern "C" void kernel_launch(void* const* d_in, const int* in_sizes, int n_in,
                              void* d_out, int out_size) {
    const float* x        = (const float*)d_in[0];
    const unsigned int* e = (const unsigned int*)d_in[1];
    const float* W1       = (const float*)d_in[2];
    const float* b1       = (const float*)d_in[3];
    const float* W2       = (const float*)d_in[4];
    const float* b2       = (const float*)d_in[5];
    const float* Wp       = (const float*)d_in[6];
    const float* bp       = (const float*)d_in[7];
    float* out            = (float*)d_out;

    // idempotent host-side attribute set (capture-safe, no allocation)
    cudaFuncSetAttribute(k_mol, cudaFuncAttributeMaxDynamicSharedMemorySize,
                         SMEM_MOL_BYTES);

    k_setup<<<1, NA>>>(e);
    k_mol<<<NB, 1024, SMEM_MOL_BYTES>>>(x, W1, b1, W2, b2, Wp, bp, out);
}

// round 13
// speedup vs baseline: 4.4151x; 1.0650x over previous
#include <cuda_runtime.h>
#include <cuda_fp16.h>
#include <cstdint>

#define NB 256
#define NA 1024
#define NE 8192
#define F1 64
#define FP 128
#define SLOPE 0.01f
#define TILE 256
#define NTILES (NA / TILE)

// ---------- device scratch (allocation-free: static globals) ----------
__device__ float          g_dinv[NA];
__device__ int            g_rowptr[NA + 1];
__device__ unsigned short g_edgesrc[NE];   // bare src index per edge (norm folded out)

__device__ __forceinline__ float leaky(float v) {
    return v >= 0.0f ? v : SLOPE * v;
}

__device__ __forceinline__ unsigned smem_u32(const void* p) {
    return (unsigned)__cvta_generic_to_shared(p);
}
__device__ __forceinline__ void ldsm_x4(unsigned addr, unsigned& r0, unsigned& r1,
                                        unsigned& r2, unsigned& r3) {
    asm volatile("ldmatrix.sync.aligned.m8n8.x4.shared.b16 {%0,%1,%2,%3}, [%4];"
                 : "=r"(r0), "=r"(r1), "=r"(r2), "=r"(r3) : "r"(addr));
}
__device__ __forceinline__ void ldsm_x4t(unsigned addr, unsigned& r0, unsigned& r1,
                                         unsigned& r2, unsigned& r3) {
    asm volatile("ldmatrix.sync.aligned.m8n8.x4.trans.shared.b16 {%0,%1,%2,%3}, [%4];"
                 : "=r"(r0), "=r"(r1), "=r"(r2), "=r"(r3) : "r"(addr));
}
__device__ __forceinline__ void mma16816(float* c, unsigned a0, unsigned a1,
                                         unsigned a2, unsigned a3,
                                         unsigned b0, unsigned b1) {
    asm volatile(
        "mma.sync.aligned.m16n8k16.row.col.f32.f16.f16.f32 "
        "{%0,%1,%2,%3}, {%4,%5,%6,%7}, {%8,%9}, {%0,%1,%2,%3};"
        : "+f"(c[0]), "+f"(c[1]), "+f"(c[2]), "+f"(c[3])
        : "r"(a0), "r"(a1), "r"(a2), "r"(a3), "r"(b0), "r"(b1));
}

// ---------- K0: degrees, dinv, CSR build (one block, warp-scan) ----------
__global__ void k_setup(const unsigned int* __restrict__ ei_raw) {
    __shared__ int   scnt[NA];
    __shared__ int   scur[NA];
    __shared__ int   warpsum[32];
    __shared__ int   s_is64;
    int tid = threadIdx.x, lane = tid & 31, wid = tid >> 5;

    if (tid < 32) {   // int64 edge_index has zero high words (values < 1024)
        unsigned m = __ballot_sync(0xffffffffu, ei_raw[2 * tid + 1] != 0u);
        if (tid == 0) s_is64 = (m == 0u);
    }
    scnt[tid] = 0;
    __syncthreads();
    const int is64 = s_is64;

    for (int e = tid; e < NE; e += NA) {
        int d = is64 ? (int)ei_raw[2 * (NE + e)] : (int)ei_raw[NE + e];
        atomicAdd(&scnt[d], 1);
    }
    __syncthreads();

    int my = scnt[tid];
    g_dinv[tid] = rsqrtf((float)(my + 1));   // deg = 1 + in-degree (self loop)

    // warp-shfl inclusive scan
    int v = my;
#pragma unroll
    for (int o = 1; o < 32; o <<= 1) {
        int t = __shfl_up_sync(0xffffffffu, v, o);
        if (lane >= o) v += t;
    }
    if (lane == 31) warpsum[wid] = v;
    __syncthreads();
    if (wid == 0) {
        int w = warpsum[lane];
#pragma unroll
        for (int o = 1; o < 32; o <<= 1) {
            int t = __shfl_up_sync(0xffffffffu, w, o);
            if (lane >= o) w += t;
        }
        warpsum[lane] = w;
    }
    __syncthreads();
    int excl = v + (wid > 0 ? warpsum[wid - 1] : 0) - my;
    scur[tid]     = excl;
    g_rowptr[tid] = excl;
    if (tid == 0) g_rowptr[NA] = NE;
    __syncthreads();

    // scatter edges: bare src index (norm factorized into node scaling)
    for (int e = tid; e < NE; e += NA) {
        int s = is64 ? (int)ei_raw[2 * e]        : (int)ei_raw[e];
        int d = is64 ? (int)ei_raw[2 * (NE + e)] : (int)ei_raw[NE + e];
        int pos = atomicAdd(&scur[d], 1);
        g_edgesrc[pos] = (unsigned short)s;
    }
}

// ---------- K1: whole network per molecule, 1024 threads ----------
#define AGG_PITCH 72   // halfs; ldmatrix conflict-free
#define SW2_OFF   (NA * F1)                        // 65536 halfs
#define SAGG_OFF  (SW2_OFF + F1 * AGG_PITCH)       // + 4608
#define SEDGE_OFF (SAGG_OFF + TILE * AGG_PITCH)    // + 18432 halfs
#define SMEM_MOL_BYTES ((SEDGE_OFF + NE) * 2)      // + 16384 B edges = 193536 B

__global__ void __launch_bounds__(1024, 1)
k_mol(const float* __restrict__ x,
      const float* __restrict__ W1, const float* __restrict__ b1,
      const float* __restrict__ W2, const float* __restrict__ b2,
      const float* __restrict__ Wp, const float* __restrict__ bp,
      float* __restrict__ outp) {
    extern __shared__ __half smh[];
    __half*         sh1   = smh;                          // [1024][64] fp16, pre-scaled by dinv
    __half*         sW2h  = smh + SW2_OFF;
    __half*         sagg  = smh + SAGG_OFF;
    unsigned short* sedge = (unsigned short*)(smh + SEDGE_OFF);
    float*          sx    = (float*)(smh + SAGG_OFF);     // alias sagg: dead before sagg used
    __shared__ float sW1[3 * F1];
    __shared__ float sb1[F1];
    __shared__ float sdinv[NA];
    __shared__ int   srow[NA + 1];
    __shared__ float pool_sm[32][32];
    __shared__ float gs[F1];

    int b = blockIdx.x;
    int tid = threadIdx.x, wid = tid >> 5, lane = tid & 31;

    // stage x (raw), edges (16 KB as int4), rowptr, dinv, W1, b1, W2(fp16)
    const float* xb = x + (size_t)b * (NA * 3);
    for (int t = tid; t < NA * 3; t += 1024) sx[t] = xb[t];
    if (tid < NE / 8)   // 1024 int4 = 16384 B
        ((int4*)sedge)[tid] = ((const int4*)g_edgesrc)[tid];
    srow[tid] = g_rowptr[tid];
    if (tid == 0) srow[NA] = NE;
    sdinv[tid] = g_dinv[tid];
    if (tid < 3 * F1) sW1[tid] = W1[tid];
    if (tid < F1)     sb1[tid] = b1[tid];
    for (int t = tid; t < F1 * F1; t += 1024) {
        int k = t >> 6, j = t & 63;
        sW2h[k * AGG_PITCH + j] = __float2half_rn(W2[t]);
    }
    __syncthreads();

    // pre-scale x by dinv (x' = dinv * x) so the gather is a plain sum
    float f = sdinv[tid];
    sx[3 * tid + 0] *= f;
    sx[3 * tid + 1] *= f;
    sx[3 * tid + 2] *= f;
    __syncthreads();

    // ---- Layer 1: thread = atom; agg_i = dinv_i*(x'_i + sum x'_j); h1' = dinv*leaky(agg@W1+b1) ----
    {
        float a0 = sx[3 * tid + 0];
        float a1 = sx[3 * tid + 1];
        float a2 = sx[3 * tid + 2];
        int r0 = srow[tid], r1 = srow[tid + 1];
#pragma unroll 4
        for (int e = r0; e < r1; e++) {
            int s3 = 3 * (int)sedge[e];
            a0 += sx[s3 + 0];
            a1 += sx[s3 + 1];
            a2 += sx[s3 + 2];
        }
        a0 *= f; a1 *= f; a2 *= f;

        // in-warp transpose: lane l writes features 2l,2l+1 of each atom row (scaled by dinv_q)
        int j2 = 2 * lane;
        int rowbase = tid & ~31;
#pragma unroll 4
        for (int q = 0; q < 32; q++) {
            float c0 = __shfl_sync(0xffffffffu, a0, q);
            float c1 = __shfl_sync(0xffffffffu, a1, q);
            float c2 = __shfl_sync(0xffffffffu, a2, q);
            float fq = __shfl_sync(0xffffffffu, f,  q);
            float v0 = c0 * sW1[j2]     + c1 * sW1[F1 + j2]     + c2 * sW1[2 * F1 + j2]     + sb1[j2];
            float v1 = c0 * sW1[j2 + 1] + c1 * sW1[F1 + j2 + 1] + c2 * sW1[2 * F1 + j2 + 1] + sb1[j2 + 1];
            ((__half2*)&sh1[(size_t)(rowbase + q) * F1])[lane] =
                __floats2half2_rn(fq * leaky(v0), fq * leaky(v1));
        }
    }
    __syncthreads();   // sh1 complete; sx dead (sagg may now be overwritten)

    // ---- Layer 2 tiles: weight-free gather(smem) + HMMA + pool ----
    const char* sh1c = (const char*)sh1 + lane * 4;   // lane's half2 within any row
    unsigned sagg_b = smem_u32(sagg);
    unsigned sw2_b  = smem_u32(sW2h);
    int m0 = (wid >> 1) * 16;
    int j0 = (wid & 1) * 32;
    int grp = lane >> 3, lr = lane & 7;
    int t4 = lane & 3;

    float pacc[4][2];
#pragma unroll
    for (int nt = 0; nt < 4; nt++) pacc[nt][0] = pacc[nt][1] = 0.0f;

    for (int tile = 0; tile < NTILES; tile++) {
        int base = tile * TILE;

        // Phase A: warp-per-atom plain-sum gather (4 instr/edge), scale once by dinv
        for (int a = wid; a < TILE; a += 32) {
            int atom = base + a;
            __half2 acc = *(const __half2*)(sh1c + (atom << 7));   // self term h1'_i
            int r0 = srow[atom], r1 = srow[atom + 1];
#pragma unroll 4
            for (int e = r0; e < r1; e++) {
                int s = (int)sedge[e];                              // LDS.U16 broadcast
                acc = __hadd2(acc, *(const __half2*)(sh1c + (s << 7)));
            }
            __half2 d2 = __float2half2_rn(sdinv[atom]);
            ((__half2*)&sagg[a * AGG_PITCH])[lane] = __hmul2(d2, acc);
        }
        __syncthreads();

        // Phase B: 256x64x64 HMMA; warp tile m16 x n32
        float c[4][4];
#pragma unroll
        for (int q = 0; q < 4; q++)
#pragma unroll
            for (int r = 0; r < 4; r++) c[q][r] = 0.0f;

#pragma unroll
        for (int kc = 0; kc < F1; kc += 16) {
            int arow = m0 + (grp & 1) * 8 + lr;
            int acol = kc + (grp >> 1) * 8;
            unsigned a0, a1, a2, a3;
            ldsm_x4(sagg_b + (arow * AGG_PITCH + acol) * 2, a0, a1, a2, a3);

            int brow = kc + (grp & 1) * 8 + lr;
#pragma unroll
            for (int p = 0; p < 2; p++) {
                int bcol = j0 + p * 16 + (grp >> 1) * 8;
                unsigned b0, b1, b2r, b3;
                ldsm_x4t(sw2_b + (brow * AGG_PITCH + bcol) * 2, b0, b1, b2r, b3);
                mma16816(c[2 * p],     a0, a1, a2, a3, b0,  b1);
                mma16816(c[2 * p + 1], a0, a1, a2, a3, b2r, b3);
            }
        }

        // bias + leaky + shfl pool-reduce; accumulate in registers across tiles
#pragma unroll
        for (int nt = 0; nt < 4; nt++) {
            int jb = j0 + nt * 8 + 2 * t4;
            float bb0 = __ldg(&b2[jb]), bb1 = __ldg(&b2[jb + 1]);
            float s0 = leaky(c[nt][0] + bb0) + leaky(c[nt][2] + bb0);
            float s1 = leaky(c[nt][1] + bb1) + leaky(c[nt][3] + bb1);
#pragma unroll
            for (int o = 4; o < 32; o <<= 1) {
                s0 += __shfl_xor_sync(0xffffffffu, s0, o);
                s1 += __shfl_xor_sync(0xffffffffu, s1, o);
            }
            pacc[nt][0] += s0;
            pacc[nt][1] += s1;
        }
        __syncthreads();   // sagg consumed; safe to overwrite next tile
    }

    // ---- write pool partials once, combine, mean, project ----
    if (lane < 4) {
#pragma unroll
        for (int nt = 0; nt < 4; nt++) {
            pool_sm[wid][nt * 8 + 2 * t4]     = pacc[nt][0];
            pool_sm[wid][nt * 8 + 2 * t4 + 1] = pacc[nt][1];
        }
    }
    __syncthreads();

    if (tid < F1) {
        int nh = tid >> 5, cw = tid & 31;
        float s = 0.0f;
#pragma unroll
        for (int m = 0; m < 16; m++) s += pool_sm[m * 2 + nh][cw];
        gs[tid] = s * (1.0f / NA);
    }
    __syncthreads();

    if (tid < FP) {
        float v = bp[tid];
#pragma unroll
        for (int k = 0; k < F1; k++) v += gs[k] * Wp[k * FP + tid];
        outp[(size_t)b * FP + tid] = leaky(v);
    }
}

// ---------- launch ----------
extern "C" void kernel_launch(void* const* d_in, const int* in_sizes, int n_in,
                              void* d_out, int out_size) {
    const float* x        = (const float*)d_in[0];
    const unsigned int* e = (const unsigned int*)d_in[1];
    const float* W1       = (const float*)d_in[2];
    const float* b1       = (const float*)d_in[3];
    const float* W2       = (const float*)d_in[4];
    const float* b2       = (const float*)d_in[5];
    const float* Wp       = (const float*)d_in[6];
    const float* bp       = (const float*)d_in[7];
    float* out            = (float*)d_out;

    // idempotent host-side attribute set (capture-safe, no allocation)
    cudaFuncSetAttribute(k_mol, cudaFuncAttributeMaxDynamicSharedMemorySize,
                         SMEM_MOL_BYTES);

    k_setup<<<1, NA>>>(e);
    k_mol<<<NB, 1024, SMEM_MOL_BYTES>>>(x, W1, b1, W2, b2, Wp, bp, out);
}

// round 15
// speedup vs baseline: 4.6564x; 1.0547x over previous
#include <cuda_runtime.h>
#include <cuda_fp16.h>
#include <cstdint>

#define NB 256
#define NA 1024
#define NE 8192
#define NEP 9216           // max padded edges (each row padded to even length)
#define F1 64
#define FP 128
#define SLOPE 0.01f
#define TILE 256
#define NTILES (NA / TILE)

// ---------- device scratch (allocation-free: static globals) ----------
__device__ float g_dinv[NA];
__device__ int   g_rowptr[NA + 1];     // padded-CSR rowptr (all even); [NA] = NE_P
__device__ int   g_edgeoff[NEP];       // per-edge byte offset: src<<7 (zero-row pad = 1024<<7)

__device__ __forceinline__ float leaky(float v) {
    return v >= 0.0f ? v : SLOPE * v;
}

__device__ __forceinline__ unsigned smem_u32(const void* p) {
    return (unsigned)__cvta_generic_to_shared(p);
}
__device__ __forceinline__ void ldsm_x4(unsigned addr, unsigned& r0, unsigned& r1,
                                        unsigned& r2, unsigned& r3) {
    asm volatile("ldmatrix.sync.aligned.m8n8.x4.shared.b16 {%0,%1,%2,%3}, [%4];"
                 : "=r"(r0), "=r"(r1), "=r"(r2), "=r"(r3) : "r"(addr));
}
__device__ __forceinline__ void ldsm_x4t(unsigned addr, unsigned& r0, unsigned& r1,
                                         unsigned& r2, unsigned& r3) {
    asm volatile("ldmatrix.sync.aligned.m8n8.x4.trans.shared.b16 {%0,%1,%2,%3}, [%4];"
                 : "=r"(r0), "=r"(r1), "=r"(r2), "=r"(r3) : "r"(addr));
}
__device__ __forceinline__ void mma16816(float* c, unsigned a0, unsigned a1,
                                         unsigned a2, unsigned a3,
                                         unsigned b0, unsigned b1) {
    asm volatile(
        "mma.sync.aligned.m16n8k16.row.col.f32.f16.f16.f32 "
        "{%0,%1,%2,%3}, {%4,%5,%6,%7}, {%8,%9}, {%0,%1,%2,%3};"
        : "+f"(c[0]), "+f"(c[1]), "+f"(c[2]), "+f"(c[3])
        : "r"(a0), "r"(a1), "r"(a2), "r"(a3), "r"(b0), "r"(b1));
}

// ---------- K0: degrees, dinv, even-padded CSR with byte offsets ----------
__global__ void k_setup(const unsigned int* __restrict__ ei_raw) {
    __shared__ int scnt[NA];
    __shared__ int scur[NA];
    __shared__ int srow[NA];
    __shared__ int warpsum[32];
    __shared__ int s_is64;
    int tid = threadIdx.x, lane = tid & 31, wid = tid >> 5;

    if (tid < 32) {   // int64 edge_index has zero high words (values < 1024)
        unsigned m = __ballot_sync(0xffffffffu, ei_raw[2 * tid + 1] != 0u);
        if (tid == 0) s_is64 = (m == 0u);
    }
    scnt[tid] = 0;
    __syncthreads();
    const int is64 = s_is64;

    for (int e = tid; e < NE; e += NA) {
        int d = is64 ? (int)ei_raw[2 * (NE + e)] : (int)ei_raw[NE + e];
        atomicAdd(&scnt[d], 1);
    }
    __syncthreads();

    int my = scnt[tid];
    g_dinv[tid] = rsqrtf((float)(my + 1));   // deg = 1 + REAL in-degree (self loop)

    int plen = (my + 1) & ~1;                // padded (even) row length

    // warp-shfl inclusive scan of padded lengths
    int v = plen;
#pragma unroll
    for (int o = 1; o < 32; o <<= 1) {
        int t = __shfl_up_sync(0xffffffffu, v, o);
        if (lane >= o) v += t;
    }
    if (lane == 31) warpsum[wid] = v;
    __syncthreads();
    if (wid == 0) {
        int w = warpsum[lane];
#pragma unroll
        for (int o = 1; o < 32; o <<= 1) {
            int t = __shfl_up_sync(0xffffffffu, w, o);
            if (lane >= o) w += t;
        }
        warpsum[lane] = w;
    }
    __syncthreads();
    int tot  = warpsum[31];
    int excl = v + (wid > 0 ? warpsum[wid - 1] : 0) - plen;
    scur[tid]     = excl;
    srow[tid]     = excl;
    g_rowptr[tid] = excl;
    if (tid == 0) g_rowptr[NA] = tot;
    __syncthreads();

    // scatter real edges as byte offsets (src<<7)
    for (int e = tid; e < NE; e += NA) {
        int s = is64 ? (int)ei_raw[2 * e]        : (int)ei_raw[e];
        int d = is64 ? (int)ei_raw[2 * (NE + e)] : (int)ei_raw[NE + e];
        int pos = atomicAdd(&scur[d], 1);
        g_edgeoff[pos] = s << 7;
    }
    __syncthreads();

    // fill padding slots with the zero row (atom NA)
    int fill_end = (tid == NA - 1) ? tot : srow[tid + 1];
    for (int p = scur[tid]; p < fill_end; p++) g_edgeoff[p] = NA << 7;
}

// ---------- K1: whole network per molecule, 1024 threads ----------
#define AGG_PITCH 72   // halfs; ldmatrix conflict-free
#define SH1_HALFS ((NA + 1) * F1)                  // 65600 halfs (incl. zero row)
#define SW2_OFF   SH1_HALFS
#define SAGG_OFF  (SW2_OFF + F1 * AGG_PITCH)       // + 4608
#define SEDGE_OFF (SAGG_OFF + TILE * AGG_PITCH)    // + 18432 halfs
#define SMEM_MOL_BYTES (SEDGE_OFF * 2 + NEP * 4)   // 177280 + 36864 = 214144 B

__global__ void __launch_bounds__(1024, 1)
k_mol(const float* __restrict__ x,
      const float* __restrict__ W1, const float* __restrict__ b1,
      const float* __restrict__ W2, const float* __restrict__ b2,
      const float* __restrict__ Wp, const float* __restrict__ bp,
      float* __restrict__ outp) {
    extern __shared__ __half smh[];
    __half* sh1   = smh;                           // [1025][64] fp16, pre-scaled by dinv
    __half* sW2h  = smh + SW2_OFF;
    __half* sagg  = smh + SAGG_OFF;
    int*    sedge = (int*)(smh + SEDGE_OFF);       // padded edge byte-offsets
    float*  sx4   = (float*)(smh + SAGG_OFF);      // [1025][4] x', aliases sagg (dead before use)
    __shared__ float sW1[3 * F1];
    __shared__ float sb1[F1];
    __shared__ float sdinv[NA];
    __shared__ int   srow[NA + 1];
    __shared__ float pool_sm[32][32];
    __shared__ float gs[F1];

    int b = blockIdx.x;
    int tid = threadIdx.x, wid = tid >> 5, lane = tid & 31;

    // stage rowptr, dinv, W1, b1, W2(fp16), edges, x' (dinv-prescaled, float4 rows)
    srow[tid] = g_rowptr[tid];
    if (tid == 0) srow[NA] = g_rowptr[NA];
    float f = g_dinv[tid];
    sdinv[tid] = f;
    if (tid < 3 * F1) sW1[tid] = W1[tid];
    if (tid < F1)     sb1[tid] = b1[tid];
    for (int t = tid; t < F1 * F1; t += 1024) {
        int k = t >> 6, j = t & 63;
        sW2h[k * AGG_PITCH + j] = __float2half_rn(W2[t]);
    }
#pragma unroll
    for (int t = tid; t < NEP; t += 1024) sedge[t] = g_edgeoff[t];
    {
        const float* xb = x + (size_t)b * (NA * 3);
        sx4[4 * tid + 0] = f * xb[3 * tid + 0];
        sx4[4 * tid + 1] = f * xb[3 * tid + 1];
        sx4[4 * tid + 2] = f * xb[3 * tid + 2];
        if (tid < 4)  sx4[4 * NA + tid] = 0.0f;            // zero x row
        if (tid < 32) ((unsigned*)(sh1 + NA * F1))[tid] = 0u;  // zero h1 row
    }
    __syncthreads();

    // ---- Layer 1: thread = atom; pair-processed gather; h1' = dinv*leaky(agg@W1+b1) ----
    {
        const char* sx4c = (const char*)sx4;
        float a0 = sx4[4 * tid + 0], a1 = sx4[4 * tid + 1], a2 = sx4[4 * tid + 2];
        float c0 = 0.0f, c1 = 0.0f, c2 = 0.0f;
        int r0 = srow[tid], r1 = srow[tid + 1];
#pragma unroll 2
        for (int e = r0; e < r1; e += 2) {
            int2 off = *(const int2*)(sedge + e);          // 2 edges per LDS.64
            float4 v0 = *(const float4*)(sx4c + (off.x >> 3));
            float4 v1 = *(const float4*)(sx4c + (off.y >> 3));
            a0 += v0.x; a1 += v0.y; a2 += v0.z;
            c0 += v1.x; c1 += v1.y; c2 += v1.z;
        }
        a0 = (a0 + c0) * f; a1 = (a1 + c1) * f; a2 = (a2 + c2) * f;

        // in-warp transpose: lane l writes features 2l,2l+1 (scaled by dinv_q)
        int j2 = 2 * lane;
        int rowbase = tid & ~31;
#pragma unroll 4
        for (int q = 0; q < 32; q++) {
            float q0 = __shfl_sync(0xffffffffu, a0, q);
            float q1 = __shfl_sync(0xffffffffu, a1, q);
            float q2 = __shfl_sync(0xffffffffu, a2, q);
            float fq = __shfl_sync(0xffffffffu, f,  q);
            float v0 = q0 * sW1[j2]     + q1 * sW1[F1 + j2]     + q2 * sW1[2 * F1 + j2]     + sb1[j2];
            float v1 = q0 * sW1[j2 + 1] + q1 * sW1[F1 + j2 + 1] + q2 * sW1[2 * F1 + j2 + 1] + sb1[j2 + 1];
            ((__half2*)&sh1[(size_t)(rowbase + q) * F1])[lane] =
                __floats2half2_rn(fq * leaky(v0), fq * leaky(v1));
        }
    }
    __syncthreads();   // sh1 complete; sx4 dead (sagg may now be overwritten)

    // ---- Layer 2 tiles: offset-direct pair gather + HMMA + pool ----
    const char* sh1c = (const char*)sh1 + lane * 4;   // lane's half2 within any row
    unsigned sagg_b = smem_u32(sagg);
    unsigned sw2_b  = smem_u32(sW2h);
    int m0 = (wid >> 1) * 16;
    int j0 = (wid & 1) * 32;
    int grp = lane >> 3, lr = lane & 7;
    int t4 = lane & 3;

    float pacc[4][2];
#pragma unroll
    for (int nt = 0; nt < 4; nt++) pacc[nt][0] = pacc[nt][1] = 0.0f;

    for (int tile = 0; tile < NTILES; tile++) {
        int base = tile * TILE;

        // Phase A: warp-per-atom pair gather; addresses are precomputed byte offsets
        for (int a = wid; a < TILE; a += 32) {
            int atom = base + a;
            __half2 acc0 = *(const __half2*)(sh1c + (atom << 7));   // self term
            __half2 acc1 = __float2half2_rn(0.0f);
            int r0 = srow[atom], r1 = srow[atom + 1];
#pragma unroll 2
            for (int e = r0; e < r1; e += 2) {
                int2 off = *(const int2*)(sedge + e);               // 2 edges per LDS.64
                acc0 = __hadd2(acc0, *(const __half2*)(sh1c + off.x));
                acc1 = __hadd2(acc1, *(const __half2*)(sh1c + off.y));
            }
            __half2 d2 = __float2half2_rn(sdinv[atom]);
            ((__half2*)&sagg[a * AGG_PITCH])[lane] = __hmul2(d2, __hadd2(acc0, acc1));
        }
        __syncthreads();

        // Phase B: 256x64x64 HMMA; warp tile m16 x n32
        float c[4][4];
#pragma unroll
        for (int q = 0; q < 4; q++)
#pragma unroll
            for (int r = 0; r < 4; r++) c[q][r] = 0.0f;

#pragma unroll
        for (int kc = 0; kc < F1; kc += 16) {
            int arow = m0 + (grp & 1) * 8 + lr;
            int acol = kc + (grp >> 1) * 8;
            unsigned a0, a1, a2, a3;
            ldsm_x4(sagg_b + (arow * AGG_PITCH + acol) * 2, a0, a1, a2, a3);

            int brow = kc + (grp & 1) * 8 + lr;
#pragma unroll
            for (int p = 0; p < 2; p++) {
                int bcol = j0 + p * 16 + (grp >> 1) * 8;
                unsigned b0, b1, b2r, b3;
                ldsm_x4t(sw2_b + (brow * AGG_PITCH + bcol) * 2, b0, b1, b2r, b3);
                mma16816(c[2 * p],     a0, a1, a2, a3, b0,  b1);
                mma16816(c[2 * p + 1], a0, a1, a2, a3, b2r, b3);
            }
        }

        // bias + leaky + shfl pool-reduce; accumulate in registers across tiles
#pragma unroll
        for (int nt = 0; nt < 4; nt++) {
            int jb = j0 + nt * 8 + 2 * t4;
            float bb0 = __ldg(&b2[jb]), bb1 = __ldg(&b2[jb + 1]);
            float s0 = leaky(c[nt][0] + bb0) + leaky(c[nt][2] + bb0);
            float s1 = leaky(c[nt][1] + bb1) + leaky(c[nt][3] + bb1);
#pragma unroll
            for (int o = 4; o < 32; o <<= 1) {
                s0 += __shfl_xor_sync(0xffffffffu, s0, o);
                s1 += __shfl_xor_sync(0xffffffffu, s1, o);
            }
            pacc[nt][0] += s0;
            pacc[nt][1] += s1;
        }
        __syncthreads();   // sagg consumed; safe to overwrite next tile
    }

    // ---- write pool partials once, combine, mean, project ----
    if (lane < 4) {
#pragma unroll
        for (int nt = 0; nt < 4; nt++) {
            pool_sm[wid][nt * 8 + 2 * t4]     = pacc[nt][0];
            pool_sm[wid][nt * 8 + 2 * t4 + 1] = pacc[nt][1];
        }
    }
    __syncthreads();

    if (tid < F1) {
        int nh = tid >> 5, cw = tid & 31;
        float s = 0.0f;
#pragma unroll
        for (int m = 0; m < 16; m++) s += pool_sm[m * 2 + nh][cw];
        gs[tid] = s * (1.0f / NA);
    }
    __syncthreads();

    if (tid < FP) {
        float v = bp[tid];
#pragma unroll
        for (int k = 0; k < F1; k++) v += gs[k] * Wp[k * FP + tid];
        outp[(size_t)b * FP + tid] = leaky(v);
    }
}

// ---------- launch ----------
extern "C" void kernel_launch(void* const* d_in, const int* in_sizes, int n_in,
                              void* d_out, int out_size) {
    const float* x        = (const float*)d_in[0];
    const unsigned int* e = (const unsigned int*)d_in[1];
    const float* W1       = (const float*)d_in[2];
    const float* b1       = (const float*)d_in[3];
    const float* W2       = (const float*)d_in[4];
    const float* b2       = (const float*)d_in[5];
    const float* Wp       = (const float*)d_in[6];
    const float* bp       = (const float*)d_in[7];
    float* out            = (float*)d_out;

    // idempotent host-side attribute set (capture-safe, no allocation)
    cudaFuncSetAttribute(k_mol, cudaFuncAttributeMaxDynamicSharedMemorySize,
                         SMEM_MOL_BYTES);

    k_setup<<<1, NA>>>(e);
    k_mol<<<NB, 1024, SMEM_MOL_BYTES>>>(x, W1, b1, W2, b2, Wp, bp, out);
}